// round 4
// baseline (speedup 1.0000x reference)
#include <cuda_runtime.h>

// ---------------------------------------------------------------------------
// SLAYER SRM-alpha SNN forward, t-major layout [t*N + n].
// R3: input-channel reductions split across lanes (shfl combine) to lift
// conv occupancy 128->256/512 blocks; fc1 64x64 tiles (304 blocks).
// ---------------------------------------------------------------------------

#define T_STEPS 300

__device__ float g_s0[16384 * T_STEPS];   // pool0 potentials -> spikes (B,2,32,32)
__device__ float g_s2[32768 * T_STEPS];   // pool1 spikes (B,16,16,16)
__device__ float g_s4[16384 * T_STEPS];   // pool2 spikes (B,32,8,8)
__device__ float g_u5[4096  * T_STEPS];   // fc1 potentials -> spikes in place
__device__ float g_u6[88    * T_STEPS];   // fc2 potentials

struct Srm { float p1, q1, p2, q2; };

__device__ __forceinline__ float srm_step(Srm& s, float u) {
    const float D  = 0.36787944117144233f;   // exp(-1)
    const float CE = 2.7182818284590452f;    // e
    const float CR = -54.365636569180905f;   // -2*theta*e
    s.q1 = __fmul_rn(D, __fadd_rn(s.q1, s.p1));
    s.p1 = __fadd_rn(__fmul_rn(D, s.p1), u);
    float y = __fmul_rn(CE, s.q1);
    s.q2 = __fmul_rn(D, __fadd_rn(s.q2, s.p2));
    float sp = (__fadd_rn(y, __fmul_rn(CR, s.q2)) >= 10.0f) ? 1.0f : 0.0f;
    s.p2 = __fadd_rn(__fmul_rn(D, s.p2), sp);
    return sp;
}

__device__ __forceinline__ void cp_async4(void* sm, const void* gm) {
    unsigned s = (unsigned)__cvta_generic_to_shared(sm);
    asm volatile("cp.async.ca.shared.global [%0], [%1], 4;" :: "r"(s), "l"(gm));
}
__device__ __forceinline__ void cp_commit() { asm volatile("cp.async.commit_group;"); }
__device__ __forceinline__ void cp_wait0()  { asm volatile("cp.async.wait_group 0;" ::: "memory"); }

// ---------------------------------------------------------------------------
// K0: 4x4 sum-pool (gain 11) + transpose (B,2,128,128,T) -> t-major g_s0.
// ---------------------------------------------------------------------------
__global__ void pool0_transpose_kernel(const float* __restrict__ x) {
    __shared__ float sm[32][33];
    const int tx = threadIdx.x, ty = threadIdx.y;
    const int tb = blockIdx.x, nb = blockIdx.y;
    const int t  = tb * 32 + tx;
    const int ho = nb & 31;
    const int bc = nb >> 5;
    for (int j = ty; j < 32; j += 8) {
        float acc = 0.f;
        if (t < T_STEPS) {
            #pragma unroll
            for (int dy = 0; dy < 4; ++dy) {
                int h = ho * 4 + dy;
                const float* rowp = x + ((bc * 128 + h) * 128 + j * 4) * T_STEPS + t;
                acc += rowp[0] + rowp[300] + rowp[600] + rowp[900];
            }
        }
        sm[j][tx] = 11.0f * acc;
    }
    __syncthreads();
    for (int jj = ty; jj < 32; jj += 8) {
        int t2 = tb * 32 + jj;
        if (t2 < T_STEPS)
            g_s0[t2 * 16384 + nb * 32 + tx] = sm[tx][jj];
    }
}

// ---- generic in-place psp+spike scan ---------------------------------------
__device__ __forceinline__ void scan_body(float* buf, int N) {
    int n = blockIdx.x * blockDim.x + threadIdx.x;
    if (n >= N) return;
    Srm st = {0.f, 0.f, 0.f, 0.f};
    #pragma unroll 1
    for (int t = 0; t < T_STEPS; ++t) {
        float u = buf[t * N + n];
        buf[t * N + n] = srm_step(st, u);
    }
}
__global__ void scan_s0_kernel() { scan_body(g_s0, 16384); }
__global__ void scan_u5_kernel() { scan_body(g_u5, 4096); }

// ---------------------------------------------------------------------------
// conv1 (5x5,pad2,2->16) + psp+spike + 2x2 pool + psp+spike, fused.
// grid (hp=16, b=8, cog=2), 256 thr: tid = co_sub*32 + xp*2 + kh.
// Thread computes the 2y x 2x conv quad for (co=cog*8+co_sub, hp, xp) over
// its input-channel half kh; halves combined via shfl_xor(1).
// ---------------------------------------------------------------------------
__global__ void __launch_bounds__(256) conv1_fused_kernel(const float* __restrict__ W1) {
    __shared__ float sbuf[2][432];        // [buf][ci*216 + r*36 + c], rows 2hp-2..2hp+3
    const int tid = threadIdx.x;
    const int kh  = tid & 1;
    const int xp  = (tid >> 1) & 15;
    const int co  = blockIdx.z * 8 + (tid >> 5);
    const int hp  = blockIdx.x;
    const int b   = blockIdx.y;
    float w[25];
    #pragma unroll
    for (int k = 0; k < 25; ++k) w[k] = W1[co * 50 + kh * 25 + k];
    for (int i = tid; i < 864; i += 256) ((float*)sbuf)[i] = 0.f;
    __syncthreads();

    const int inBase = b * 2048;
    {   // stage frame 0
        const float* fr = g_s0 + inBase;
        for (int i = tid; i < 432; i += 256) {
            int ci = i / 216, rem = i - ci * 216, r = rem / 36, c = rem - r * 36;
            int row = 2 * hp + r - 2, col = c - 2;
            if (row >= 0 && row < 32 && col >= 0 && col < 32)
                cp_async4(&sbuf[0][i], fr + ci * 1024 + row * 32 + col);
        }
        cp_commit(); cp_wait0();
    }
    __syncthreads();

    Srm c00 = {0,0,0,0}, c01 = {0,0,0,0}, c10 = {0,0,0,0}, c11 = {0,0,0,0}, pl = {0,0,0,0};
    const int outIdx = ((b * 16 + co) * 16 + hp) * 16 + xp;

    #pragma unroll 1
    for (int t = 0; t < T_STEPS; ++t) {
        const int cur = t & 1;
        if (t + 1 < T_STEPS) {
            const float* fr = g_s0 + (t + 1) * 16384 + inBase;
            for (int i = tid; i < 432; i += 256) {
                int ci = i / 216, rem = i - ci * 216, r = rem / 36, c = rem - r * 36;
                int row = 2 * hp + r - 2, col = c - 2;
                if (row >= 0 && row < 32 && col >= 0 && col < 32)
                    cp_async4(&sbuf[cur ^ 1][i], fr + ci * 1024 + row * 32 + col);
            }
        }
        cp_commit();

        float a00 = 0.f, a01 = 0.f, a10 = 0.f, a11 = 0.f;
        {
            const float* sp_ = &sbuf[cur][kh * 216 + 2 * xp];
            #pragma unroll
            for (int r = 0; r < 6; ++r) {
                float2 p0 = *(const float2*)(sp_ + r * 36);
                float2 p1 = *(const float2*)(sp_ + r * 36 + 2);
                float2 p2 = *(const float2*)(sp_ + r * 36 + 4);
                float v[6] = {p0.x, p0.y, p1.x, p1.y, p2.x, p2.y};
                if (r < 5) {                       // y0: ky = r
                    const int kb = r * 5;
                    #pragma unroll
                    for (int kx = 0; kx < 5; ++kx) {
                        a00 = fmaf(v[kx],     w[kb + kx], a00);
                        a01 = fmaf(v[kx + 1], w[kb + kx], a01);
                    }
                }
                if (r >= 1) {                      // y1: ky = r-1
                    const int kb = (r - 1) * 5;
                    #pragma unroll
                    for (int kx = 0; kx < 5; ++kx) {
                        a10 = fmaf(v[kx],     w[kb + kx], a10);
                        a11 = fmaf(v[kx + 1], w[kb + kx], a11);
                    }
                }
            }
        }
        // combine input-channel halves (commutative -> bitwise identical lanes)
        a00 += __shfl_xor_sync(0xffffffffu, a00, 1);
        a01 += __shfl_xor_sync(0xffffffffu, a01, 1);
        a10 += __shfl_xor_sync(0xffffffffu, a10, 1);
        a11 += __shfl_xor_sync(0xffffffffu, a11, 1);

        float s00 = srm_step(c00, a00), s01 = srm_step(c01, a01);
        float s10 = srm_step(c10, a10), s11 = srm_step(c11, a11);
        float u = 11.0f * ((s00 + s01) + (s10 + s11));
        float sp = srm_step(pl, u);
        if (kh == 0) g_s2[t * 32768 + outIdx] = sp;

        cp_wait0();
        __syncthreads();
    }
}

// ---------------------------------------------------------------------------
// conv2 (3x3,pad1,16->32) + psp+spike + 2x2 pool + psp+spike, fused.
// grid (hp=8, b=8, z=xh*4+cog), 128 thr: tid = co_sub*16 + xp*4 + kq.
// Thread computes the conv quad for (co=cog*8+co_sub, hp, xh*4+xp) over its
// input-channel quarter kq; quarters combined via shfl_xor(1), shfl_xor(2).
// ---------------------------------------------------------------------------
__global__ void __launch_bounds__(128) conv2_fused_kernel(const float* __restrict__ W2) {
    __shared__ float sbuf[2][640];        // [buf][ci*40 + r*10 + c], rows 2hp-1..2hp+2
    const int tid = threadIdx.x;
    const int kq  = tid & 3;
    const int xp  = (tid >> 2) & 3;
    const int co  = (blockIdx.z & 3) * 8 + (tid >> 4);
    const int xh  = blockIdx.z >> 2;      // 0..1
    const int hp  = blockIdx.x;           // 0..7
    const int b   = blockIdx.y;
    float w[36];
    #pragma unroll
    for (int k = 0; k < 36; ++k) w[k] = W2[co * 144 + kq * 36 + k];
    for (int i = tid; i < 1280; i += 128) ((float*)sbuf)[i] = 0.f;
    __syncthreads();

    const int inBase = b * 4096;
    {   // stage frame 0
        const float* fr = g_s2 + inBase;
        for (int i = tid; i < 640; i += 128) {
            int ci = i / 40, rem = i - ci * 40, r = rem / 10, c = rem - r * 10;
            int row = 2 * hp + r - 1, col = xh * 8 + c - 1;
            if (row >= 0 && row < 16 && col >= 0 && col < 16)
                cp_async4(&sbuf[0][i], fr + ci * 256 + row * 16 + col);
        }
        cp_commit(); cp_wait0();
    }
    __syncthreads();

    Srm c00 = {0,0,0,0}, c01 = {0,0,0,0}, c10 = {0,0,0,0}, c11 = {0,0,0,0}, pl = {0,0,0,0};
    const int outIdx = ((b * 32 + co) * 8 + hp) * 8 + xh * 4 + xp;

    #pragma unroll 1
    for (int t = 0; t < T_STEPS; ++t) {
        const int cur = t & 1;
        if (t + 1 < T_STEPS) {
            const float* fr = g_s2 + (t + 1) * 32768 + inBase;
            for (int i = tid; i < 640; i += 128) {
                int ci = i / 40, rem = i - ci * 40, r = rem / 10, c = rem - r * 10;
                int row = 2 * hp + r - 1, col = xh * 8 + c - 1;
                if (row >= 0 && row < 16 && col >= 0 && col < 16)
                    cp_async4(&sbuf[cur ^ 1][i], fr + ci * 256 + row * 16 + col);
            }
        }
        cp_commit();

        float a00 = 0.f, a01 = 0.f, a10 = 0.f, a11 = 0.f;
        #pragma unroll
        for (int lci = 0; lci < 4; ++lci) {
            const float* sp_ = &sbuf[cur][(kq * 4 + lci) * 40 + 2 * xp];
            #pragma unroll
            for (int r = 0; r < 4; ++r) {
                float2 p0 = *(const float2*)(sp_ + r * 10);
                float2 p1 = *(const float2*)(sp_ + r * 10 + 2);
                float v[4] = {p0.x, p0.y, p1.x, p1.y};
                if (r < 3) {                       // y0: ky = r
                    const int kb = lci * 9 + r * 3;
                    #pragma unroll
                    for (int kx = 0; kx < 3; ++kx) {
                        a00 = fmaf(v[kx],     w[kb + kx], a00);
                        a01 = fmaf(v[kx + 1], w[kb + kx], a01);
                    }
                }
                if (r >= 1) {                      // y1: ky = r-1
                    const int kb = lci * 9 + (r - 1) * 3;
                    #pragma unroll
                    for (int kx = 0; kx < 3; ++kx) {
                        a10 = fmaf(v[kx],     w[kb + kx], a10);
                        a11 = fmaf(v[kx + 1], w[kb + kx], a11);
                    }
                }
            }
        }
        // combine quarters: ((q0+q1)+(q2+q3)), identical on all 4 lanes
        a00 += __shfl_xor_sync(0xffffffffu, a00, 1);
        a01 += __shfl_xor_sync(0xffffffffu, a01, 1);
        a10 += __shfl_xor_sync(0xffffffffu, a10, 1);
        a11 += __shfl_xor_sync(0xffffffffu, a11, 1);
        a00 += __shfl_xor_sync(0xffffffffu, a00, 2);
        a01 += __shfl_xor_sync(0xffffffffu, a01, 2);
        a10 += __shfl_xor_sync(0xffffffffu, a10, 2);
        a11 += __shfl_xor_sync(0xffffffffu, a11, 2);

        float s00 = srm_step(c00, a00), s01 = srm_step(c01, a01);
        float s10 = srm_step(c10, a10), s11 = srm_step(c11, a11);
        float u = 11.0f * ((s00 + s01) + (s10 + s11));
        float sp = srm_step(pl, u);
        if (kq == 0) g_s4[t * 16384 + outIdx] = sp;

        cp_wait0();
        __syncthreads();
    }
}

// ---------------------------------------------------------------------------
// fc1 GEMM: rows=(t,b) 2400, K=2048, N=512. 64x64 tile, 4x4 micro, kc=32,
// register double-buffered global loads, LDS.128 inner loop. 304 blocks.
// ---------------------------------------------------------------------------
__global__ void __launch_bounds__(256) fc1_gemm_kernel(const float* __restrict__ Wf1) {
    __shared__ float As[32 * 68];
    __shared__ float Bs[32 * 68];
    const int tid = threadIdx.x;
    const int txn = tid & 15, tym = tid >> 4;
    const int m0 = blockIdx.x * 64, n0 = blockIdx.y * 64;
    float acc[4][4];
    #pragma unroll
    for (int i = 0; i < 4; ++i)
        #pragma unroll
        for (int j = 0; j < 4; ++j) acc[i][j] = 0.f;

    float4 ra[2], rb[2];
    #pragma unroll
    for (int e = 0; e < 2; ++e) {
        int i = tid + e * 256, m = i >> 3, kq = i & 7, row = m0 + m;
        ra[e] = (row < 2400) ? *(const float4*)(g_s4 + row * 2048 + kq * 4)
                             : make_float4(0.f, 0.f, 0.f, 0.f);
        rb[e] = *(const float4*)(Wf1 + (n0 + m) * 2048 + kq * 4);
    }

    for (int kb = 0; kb < 2048; kb += 32) {
        #pragma unroll
        for (int e = 0; e < 2; ++e) {
            int i = tid + e * 256, m = i >> 3, kq = i & 7;
            As[(kq * 4 + 0) * 68 + m] = ra[e].x;
            As[(kq * 4 + 1) * 68 + m] = ra[e].y;
            As[(kq * 4 + 2) * 68 + m] = ra[e].z;
            As[(kq * 4 + 3) * 68 + m] = ra[e].w;
            Bs[(kq * 4 + 0) * 68 + m] = rb[e].x;
            Bs[(kq * 4 + 1) * 68 + m] = rb[e].y;
            Bs[(kq * 4 + 2) * 68 + m] = rb[e].z;
            Bs[(kq * 4 + 3) * 68 + m] = rb[e].w;
        }
        __syncthreads();
        if (kb + 32 < 2048) {
            #pragma unroll
            for (int e = 0; e < 2; ++e) {
                int i = tid + e * 256, m = i >> 3, kq = i & 7, row = m0 + m;
                ra[e] = (row < 2400) ? *(const float4*)(g_s4 + row * 2048 + kb + 32 + kq * 4)
                                     : make_float4(0.f, 0.f, 0.f, 0.f);
                rb[e] = *(const float4*)(Wf1 + (n0 + m) * 2048 + kb + 32 + kq * 4);
            }
        }
        #pragma unroll
        for (int k = 0; k < 32; ++k) {
            float4 aq = *(const float4*)&As[k * 68 + tym * 4];
            float4 bq = *(const float4*)&Bs[k * 68 + txn * 4];
            float av[4] = {aq.x, aq.y, aq.z, aq.w};
            float bv[4] = {bq.x, bq.y, bq.z, bq.w};
            #pragma unroll
            for (int i = 0; i < 4; ++i)
                #pragma unroll
                for (int j = 0; j < 4; ++j)
                    acc[i][j] = fmaf(av[i], bv[j], acc[i][j]);
        }
        __syncthreads();
    }
    #pragma unroll
    for (int i = 0; i < 4; ++i) {
        int row = m0 + tym * 4 + i;
        if (row < 2400) {
            float4 v = make_float4(acc[i][0], acc[i][1], acc[i][2], acc[i][3]);
            *(float4*)(g_u5 + row * 512 + n0 + txn * 4) = v;
        }
    }
}

// ---------------------------------------------------------------------------
__global__ void fc2_kernel(const float* __restrict__ Wf2) {
    int idx = blockIdx.x * 256 + threadIdx.x;
    if (idx >= 2400 * 11) return;
    int row = idx / 11, o = idx % 11;
    const float* a  = g_u5 + row * 512;
    const float* wv = Wf2 + o * 512;
    float acc = 0.f;
    #pragma unroll 8
    for (int c = 0; c < 512; ++c) acc = fmaf(a[c], wv[c], acc);
    g_u6[idx] = acc;
}

__global__ void final_scan_kernel(float* __restrict__ out) {
    int n = threadIdx.x;
    if (n >= 88) return;
    Srm st = {0.f, 0.f, 0.f, 0.f};
    #pragma unroll 1
    for (int t = 0; t < T_STEPS; ++t) {
        float s = srm_step(st, g_u6[t * 88 + n]);
        out[n * 300 + t] = s;
    }
}

// ---------------------------------------------------------------------------
extern "C" void kernel_launch(void* const* d_in, const int* in_sizes, int n_in,
                              void* d_out, int out_size) {
    (void)in_sizes; (void)n_in; (void)out_size;
    const float* s_in = (const float*)d_in[0];
    const float* W1   = (const float*)d_in[1];
    const float* W2   = (const float*)d_in[2];
    const float* Wf1  = (const float*)d_in[3];
    const float* Wf2  = (const float*)d_in[4];
    float* out = (float*)d_out;

    pool0_transpose_kernel<<<dim3(10, 512), dim3(32, 8)>>>(s_in);
    scan_s0_kernel<<<128, 128>>>();
    conv1_fused_kernel<<<dim3(16, 8, 2), 256>>>(W1);
    conv2_fused_kernel<<<dim3(8, 8, 8), 128>>>(W2);
    fc1_gemm_kernel<<<dim3(38, 8), 256>>>(Wf1);
    scan_u5_kernel<<<32, 128>>>();
    fc2_kernel<<<104, 256>>>(Wf2);
    final_scan_kernel<<<1, 128>>>(out);
}

// round 5
// speedup vs baseline: 1.0595x; 1.0595x over previous
#include <cuda_runtime.h>

// ---------------------------------------------------------------------------
// SLAYER SRM-alpha SNN forward, t-major layout [t*N + n].
// R4: k-split folded INSIDE 512-thread blocks (one staged tile shared by all
// warps); staging offsets/predicates precomputed outside the t-loop.
// ---------------------------------------------------------------------------

#define T_STEPS 300

__device__ float g_s0[16384 * T_STEPS];   // pool0 potentials -> spikes (B,2,32,32)
__device__ float g_s2[32768 * T_STEPS];   // pool1 spikes (B,16,16,16)
__device__ float g_s4[16384 * T_STEPS];   // pool2 spikes (B,32,8,8)
__device__ float g_u5[4096  * T_STEPS];   // fc1 potentials -> spikes in place
__device__ float g_u6[88    * T_STEPS];   // fc2 potentials

struct Srm { float p1, q1, p2, q2; };

__device__ __forceinline__ float srm_step(Srm& s, float u) {
    const float D  = 0.36787944117144233f;   // exp(-1)
    const float CE = 2.7182818284590452f;    // e
    const float CR = -54.365636569180905f;   // -2*theta*e
    s.q1 = __fmul_rn(D, __fadd_rn(s.q1, s.p1));
    s.p1 = __fadd_rn(__fmul_rn(D, s.p1), u);
    float y = __fmul_rn(CE, s.q1);
    s.q2 = __fmul_rn(D, __fadd_rn(s.q2, s.p2));
    float sp = (__fadd_rn(y, __fmul_rn(CR, s.q2)) >= 10.0f) ? 1.0f : 0.0f;
    s.p2 = __fadd_rn(__fmul_rn(D, s.p2), sp);
    return sp;
}

__device__ __forceinline__ void cp_async4(void* sm, const void* gm) {
    unsigned s = (unsigned)__cvta_generic_to_shared(sm);
    asm volatile("cp.async.ca.shared.global [%0], [%1], 4;" :: "r"(s), "l"(gm));
}
__device__ __forceinline__ void cp_commit() { asm volatile("cp.async.commit_group;"); }
__device__ __forceinline__ void cp_wait0()  { asm volatile("cp.async.wait_group 0;" ::: "memory"); }

// ---------------------------------------------------------------------------
// K0: 4x4 sum-pool (gain 11) + transpose (B,2,128,128,T) -> t-major g_s0.
// ---------------------------------------------------------------------------
__global__ void pool0_transpose_kernel(const float* __restrict__ x) {
    __shared__ float sm[32][33];
    const int tx = threadIdx.x, ty = threadIdx.y;
    const int tb = blockIdx.x, nb = blockIdx.y;
    const int t  = tb * 32 + tx;
    const int ho = nb & 31;
    const int bc = nb >> 5;
    for (int j = ty; j < 32; j += 8) {
        float acc = 0.f;
        if (t < T_STEPS) {
            #pragma unroll
            for (int dy = 0; dy < 4; ++dy) {
                int h = ho * 4 + dy;
                const float* rowp = x + ((bc * 128 + h) * 128 + j * 4) * T_STEPS + t;
                acc += rowp[0] + rowp[300] + rowp[600] + rowp[900];
            }
        }
        sm[j][tx] = 11.0f * acc;
    }
    __syncthreads();
    for (int jj = ty; jj < 32; jj += 8) {
        int t2 = tb * 32 + jj;
        if (t2 < T_STEPS)
            g_s0[t2 * 16384 + nb * 32 + tx] = sm[tx][jj];
    }
}

// ---- generic in-place psp+spike scan ---------------------------------------
__device__ __forceinline__ void scan_body(float* buf, int N) {
    int n = blockIdx.x * blockDim.x + threadIdx.x;
    if (n >= N) return;
    Srm st = {0.f, 0.f, 0.f, 0.f};
    #pragma unroll 1
    for (int t = 0; t < T_STEPS; ++t) {
        float u = buf[t * N + n];
        buf[t * N + n] = srm_step(st, u);
    }
}
__global__ void scan_s0_kernel() { scan_body(g_s0, 16384); }
__global__ void scan_u5_kernel() { scan_body(g_u5, 4096); }

// ---------------------------------------------------------------------------
// conv1 (5x5,pad2,2->16) + psp+spike + 2x2 pool + psp+spike, fused.
// grid (hp=16, b=8), 512 thr: tid = co*32 + xp*2 + kh.
// One staged tile (432 floats) shared by all 16 warps; kh halves combined
// with shfl_xor(1). Staging offsets precomputed outside the t-loop.
// ---------------------------------------------------------------------------
__global__ void __launch_bounds__(512) conv1_fused_kernel(const float* __restrict__ W1) {
    __shared__ float sbuf[2][432];        // [buf][ci*216 + r*36 + c], rows 2hp-2..2hp+3
    const int tid = threadIdx.x;
    const int kh  = tid & 1;
    const int xp  = (tid >> 1) & 15;
    const int co  = tid >> 5;
    const int hp  = blockIdx.x;
    const int b   = blockIdx.y;
    float w[25];
    #pragma unroll
    for (int k = 0; k < 25; ++k) w[k] = W1[co * 50 + kh * 25 + k];
    for (int i = tid; i < 864; i += 512) ((float*)sbuf)[i] = 0.f;

    // precompute this thread's staging slot (1 elem, tid<432)
    bool sv = false; int gOff = 0;
    if (tid < 432) {
        int ci = tid / 216, rem = tid - ci * 216, r = rem / 36, c = rem - r * 36;
        int row = 2 * hp + r - 2, col = c - 2;
        if (row >= 0 && row < 32 && col >= 0 && col < 32) {
            sv = true;
            gOff = b * 2048 + ci * 1024 + row * 32 + col;
        }
    }
    __syncthreads();

    if (sv) cp_async4(&sbuf[0][tid], g_s0 + gOff);
    cp_commit(); cp_wait0();
    __syncthreads();

    Srm c00 = {0,0,0,0}, c01 = {0,0,0,0}, c10 = {0,0,0,0}, c11 = {0,0,0,0}, pl = {0,0,0,0};
    const int outIdx = ((b * 16 + co) * 16 + hp) * 16 + xp;

    #pragma unroll 1
    for (int t = 0; t < T_STEPS; ++t) {
        const int cur = t & 1;
        if (sv && t + 1 < T_STEPS)
            cp_async4(&sbuf[cur ^ 1][tid], g_s0 + (t + 1) * 16384 + gOff);
        cp_commit();

        float a00 = 0.f, a01 = 0.f, a10 = 0.f, a11 = 0.f;
        {
            const float* sp_ = &sbuf[cur][kh * 216 + 2 * xp];
            #pragma unroll
            for (int r = 0; r < 6; ++r) {
                float2 p0 = *(const float2*)(sp_ + r * 36);
                float2 p1 = *(const float2*)(sp_ + r * 36 + 2);
                float2 p2 = *(const float2*)(sp_ + r * 36 + 4);
                float v[6] = {p0.x, p0.y, p1.x, p1.y, p2.x, p2.y};
                if (r < 5) {                       // y0: ky = r
                    const int kb = r * 5;
                    #pragma unroll
                    for (int kx = 0; kx < 5; ++kx) {
                        a00 = fmaf(v[kx],     w[kb + kx], a00);
                        a01 = fmaf(v[kx + 1], w[kb + kx], a01);
                    }
                }
                if (r >= 1) {                      // y1: ky = r-1
                    const int kb = (r - 1) * 5;
                    #pragma unroll
                    for (int kx = 0; kx < 5; ++kx) {
                        a10 = fmaf(v[kx],     w[kb + kx], a10);
                        a11 = fmaf(v[kx + 1], w[kb + kx], a11);
                    }
                }
            }
        }
        a00 += __shfl_xor_sync(0xffffffffu, a00, 1);
        a01 += __shfl_xor_sync(0xffffffffu, a01, 1);
        a10 += __shfl_xor_sync(0xffffffffu, a10, 1);
        a11 += __shfl_xor_sync(0xffffffffu, a11, 1);

        float s00 = srm_step(c00, a00), s01 = srm_step(c01, a01);
        float s10 = srm_step(c10, a10), s11 = srm_step(c11, a11);
        float u = 11.0f * ((s00 + s01) + (s10 + s11));
        float sp = srm_step(pl, u);
        if (kh == 0) g_s2[t * 32768 + outIdx] = sp;

        cp_wait0();
        __syncthreads();
    }
}

// ---------------------------------------------------------------------------
// conv2 (3x3,pad1,16->32) + psp+spike + 2x2 pool + psp+spike, fused.
// grid (hp=8, b=8, xh=2), 512 thr: tid = co*16 + xp*4 + kq.
// One staged tile (640 floats) shared by all 16 warps; kq quarters combined
// with shfl_xor(1),(2). Staging offsets precomputed outside the t-loop.
// ---------------------------------------------------------------------------
__global__ void __launch_bounds__(512) conv2_fused_kernel(const float* __restrict__ W2) {
    __shared__ float sbuf[2][640];        // [buf][ci*40 + r*10 + c], rows 2hp-1..2hp+2
    const int tid = threadIdx.x;
    const int kq  = tid & 3;
    const int xp  = (tid >> 2) & 3;
    const int co  = tid >> 4;             // 0..31
    const int hp  = blockIdx.x;           // 0..7
    const int b   = blockIdx.y;
    const int xh  = blockIdx.z;           // 0..1
    float w[36];
    #pragma unroll
    for (int k = 0; k < 36; ++k) w[k] = W2[co * 144 + kq * 36 + k];
    for (int i = tid; i < 1280; i += 512) ((float*)sbuf)[i] = 0.f;

    // precompute staging slots: elems tid and tid+512 (if < 640)
    bool sv0 = false, sv1 = false; int g0 = 0, g1 = 0;
    {
        int i = tid;
        int ci = i / 40, rem = i - ci * 40, r = rem / 10, c = rem - r * 10;
        int row = 2 * hp + r - 1, col = xh * 8 + c - 1;
        if (row >= 0 && row < 16 && col >= 0 && col < 16) {
            sv0 = true; g0 = b * 4096 + ci * 256 + row * 16 + col;
        }
    }
    if (tid + 512 < 640) {
        int i = tid + 512;
        int ci = i / 40, rem = i - ci * 40, r = rem / 10, c = rem - r * 10;
        int row = 2 * hp + r - 1, col = xh * 8 + c - 1;
        if (row >= 0 && row < 16 && col >= 0 && col < 16) {
            sv1 = true; g1 = b * 4096 + ci * 256 + row * 16 + col;
        }
    }
    __syncthreads();

    if (sv0) cp_async4(&sbuf[0][tid],       g_s2 + g0);
    if (sv1) cp_async4(&sbuf[0][tid + 512], g_s2 + g1);
    cp_commit(); cp_wait0();
    __syncthreads();

    Srm c00 = {0,0,0,0}, c01 = {0,0,0,0}, c10 = {0,0,0,0}, c11 = {0,0,0,0}, pl = {0,0,0,0};
    const int outIdx = ((b * 32 + co) * 8 + hp) * 8 + xh * 4 + xp;

    #pragma unroll 1
    for (int t = 0; t < T_STEPS; ++t) {
        const int cur = t & 1;
        if (t + 1 < T_STEPS) {
            const float* fr = g_s2 + (t + 1) * 32768;
            if (sv0) cp_async4(&sbuf[cur ^ 1][tid],       fr + g0);
            if (sv1) cp_async4(&sbuf[cur ^ 1][tid + 512], fr + g1);
        }
        cp_commit();

        float a00 = 0.f, a01 = 0.f, a10 = 0.f, a11 = 0.f;
        #pragma unroll
        for (int lci = 0; lci < 4; ++lci) {
            const float* sp_ = &sbuf[cur][(kq * 4 + lci) * 40 + 2 * xp];
            #pragma unroll
            for (int r = 0; r < 4; ++r) {
                float2 p0 = *(const float2*)(sp_ + r * 10);
                float2 p1 = *(const float2*)(sp_ + r * 10 + 2);
                float v[4] = {p0.x, p0.y, p1.x, p1.y};
                if (r < 3) {                       // y0: ky = r
                    const int kb = lci * 9 + r * 3;
                    #pragma unroll
                    for (int kx = 0; kx < 3; ++kx) {
                        a00 = fmaf(v[kx],     w[kb + kx], a00);
                        a01 = fmaf(v[kx + 1], w[kb + kx], a01);
                    }
                }
                if (r >= 1) {                      // y1: ky = r-1
                    const int kb = lci * 9 + (r - 1) * 3;
                    #pragma unroll
                    for (int kx = 0; kx < 3; ++kx) {
                        a10 = fmaf(v[kx],     w[kb + kx], a10);
                        a11 = fmaf(v[kx + 1], w[kb + kx], a11);
                    }
                }
            }
        }
        a00 += __shfl_xor_sync(0xffffffffu, a00, 1);
        a01 += __shfl_xor_sync(0xffffffffu, a01, 1);
        a10 += __shfl_xor_sync(0xffffffffu, a10, 1);
        a11 += __shfl_xor_sync(0xffffffffu, a11, 1);
        a00 += __shfl_xor_sync(0xffffffffu, a00, 2);
        a01 += __shfl_xor_sync(0xffffffffu, a01, 2);
        a10 += __shfl_xor_sync(0xffffffffu, a10, 2);
        a11 += __shfl_xor_sync(0xffffffffu, a11, 2);

        float s00 = srm_step(c00, a00), s01 = srm_step(c01, a01);
        float s10 = srm_step(c10, a10), s11 = srm_step(c11, a11);
        float u = 11.0f * ((s00 + s01) + (s10 + s11));
        float sp = srm_step(pl, u);
        if (kq == 0) g_s4[t * 16384 + outIdx] = sp;

        cp_wait0();
        __syncthreads();
    }
}

// ---------------------------------------------------------------------------
// fc1 GEMM: rows=(t,b) 2400, K=2048, N=512. 64x64 tile, 4x4 micro, kc=32,
// register double-buffered global loads, LDS.128 inner loop. 304 blocks.
// ---------------------------------------------------------------------------
__global__ void __launch_bounds__(256) fc1_gemm_kernel(const float* __restrict__ Wf1) {
    __shared__ float As[32 * 68];
    __shared__ float Bs[32 * 68];
    const int tid = threadIdx.x;
    const int txn = tid & 15, tym = tid >> 4;
    const int m0 = blockIdx.x * 64, n0 = blockIdx.y * 64;
    float acc[4][4];
    #pragma unroll
    for (int i = 0; i < 4; ++i)
        #pragma unroll
        for (int j = 0; j < 4; ++j) acc[i][j] = 0.f;

    float4 ra[2], rb[2];
    #pragma unroll
    for (int e = 0; e < 2; ++e) {
        int i = tid + e * 256, m = i >> 3, kq = i & 7, row = m0 + m;
        ra[e] = (row < 2400) ? *(const float4*)(g_s4 + row * 2048 + kq * 4)
                             : make_float4(0.f, 0.f, 0.f, 0.f);
        rb[e] = *(const float4*)(Wf1 + (n0 + m) * 2048 + kq * 4);
    }

    for (int kb = 0; kb < 2048; kb += 32) {
        #pragma unroll
        for (int e = 0; e < 2; ++e) {
            int i = tid + e * 256, m = i >> 3, kq = i & 7;
            As[(kq * 4 + 0) * 68 + m] = ra[e].x;
            As[(kq * 4 + 1) * 68 + m] = ra[e].y;
            As[(kq * 4 + 2) * 68 + m] = ra[e].z;
            As[(kq * 4 + 3) * 68 + m] = ra[e].w;
            Bs[(kq * 4 + 0) * 68 + m] = rb[e].x;
            Bs[(kq * 4 + 1) * 68 + m] = rb[e].y;
            Bs[(kq * 4 + 2) * 68 + m] = rb[e].z;
            Bs[(kq * 4 + 3) * 68 + m] = rb[e].w;
        }
        __syncthreads();
        if (kb + 32 < 2048) {
            #pragma unroll
            for (int e = 0; e < 2; ++e) {
                int i = tid + e * 256, m = i >> 3, kq = i & 7, row = m0 + m;
                ra[e] = (row < 2400) ? *(const float4*)(g_s4 + row * 2048 + kb + 32 + kq * 4)
                                     : make_float4(0.f, 0.f, 0.f, 0.f);
                rb[e] = *(const float4*)(Wf1 + (n0 + m) * 2048 + kb + 32 + kq * 4);
            }
        }
        #pragma unroll
        for (int k = 0; k < 32; ++k) {
            float4 aq = *(const float4*)&As[k * 68 + tym * 4];
            float4 bq = *(const float4*)&Bs[k * 68 + txn * 4];
            float av[4] = {aq.x, aq.y, aq.z, aq.w};
            float bv[4] = {bq.x, bq.y, bq.z, bq.w};
            #pragma unroll
            for (int i = 0; i < 4; ++i)
                #pragma unroll
                for (int j = 0; j < 4; ++j)
                    acc[i][j] = fmaf(av[i], bv[j], acc[i][j]);
        }
        __syncthreads();
    }
    #pragma unroll
    for (int i = 0; i < 4; ++i) {
        int row = m0 + tym * 4 + i;
        if (row < 2400) {
            float4 v = make_float4(acc[i][0], acc[i][1], acc[i][2], acc[i][3]);
            *(float4*)(g_u5 + row * 512 + n0 + txn * 4) = v;
        }
    }
}

// ---------------------------------------------------------------------------
__global__ void fc2_kernel(const float* __restrict__ Wf2) {
    int idx = blockIdx.x * 256 + threadIdx.x;
    if (idx >= 2400 * 11) return;
    int row = idx / 11, o = idx % 11;
    const float* a  = g_u5 + row * 512;
    const float* wv = Wf2 + o * 512;
    float acc = 0.f;
    #pragma unroll 8
    for (int c = 0; c < 512; ++c) acc = fmaf(a[c], wv[c], acc);
    g_u6[idx] = acc;
}

__global__ void final_scan_kernel(float* __restrict__ out) {
    int n = threadIdx.x;
    if (n >= 88) return;
    Srm st = {0.f, 0.f, 0.f, 0.f};
    #pragma unroll 1
    for (int t = 0; t < T_STEPS; ++t) {
        float s = srm_step(st, g_u6[t * 88 + n]);
        out[n * 300 + t] = s;
    }
}

// ---------------------------------------------------------------------------
extern "C" void kernel_launch(void* const* d_in, const int* in_sizes, int n_in,
                              void* d_out, int out_size) {
    (void)in_sizes; (void)n_in; (void)out_size;
    const float* s_in = (const float*)d_in[0];
    const float* W1   = (const float*)d_in[1];
    const float* W2   = (const float*)d_in[2];
    const float* Wf1  = (const float*)d_in[3];
    const float* Wf2  = (const float*)d_in[4];
    float* out = (float*)d_out;

    pool0_transpose_kernel<<<dim3(10, 512), dim3(32, 8)>>>(s_in);
    scan_s0_kernel<<<128, 128>>>();
    conv1_fused_kernel<<<dim3(16, 8), 512>>>(W1);
    conv2_fused_kernel<<<dim3(8, 8, 2), 512>>>(W2);
    fc1_gemm_kernel<<<dim3(38, 8), 256>>>(Wf1);
    scan_u5_kernel<<<32, 128>>>();
    fc2_kernel<<<104, 256>>>(Wf2);
    final_scan_kernel<<<1, 128>>>(out);
}

// round 6
// speedup vs baseline: 1.5540x; 1.4668x over previous
#include <cuda_runtime.h>

// ---------------------------------------------------------------------------
// SLAYER SRM-alpha SNN forward, t-major layout [t*N + n].
// R5: fix LDS bank conflicts from k-split: kq/kh moved to HIGH lane bits,
// conv2 smem channel stride padded 40->42 (kq quarters -> banks 0/8/16/24).
// ---------------------------------------------------------------------------

#define T_STEPS 300

__device__ float g_s0[16384 * T_STEPS];   // pool0 potentials -> spikes (B,2,32,32)
__device__ float g_s2[32768 * T_STEPS];   // pool1 spikes (B,16,16,16)
__device__ float g_s4[16384 * T_STEPS];   // pool2 spikes (B,32,8,8)
__device__ float g_u5[4096  * T_STEPS];   // fc1 potentials -> spikes in place
__device__ float g_u6[88    * T_STEPS];   // fc2 potentials

struct Srm { float p1, q1, p2, q2; };

__device__ __forceinline__ float srm_step(Srm& s, float u) {
    const float D  = 0.36787944117144233f;   // exp(-1)
    const float CE = 2.7182818284590452f;    // e
    const float CR = -54.365636569180905f;   // -2*theta*e
    s.q1 = __fmul_rn(D, __fadd_rn(s.q1, s.p1));
    s.p1 = __fadd_rn(__fmul_rn(D, s.p1), u);
    float y = __fmul_rn(CE, s.q1);
    s.q2 = __fmul_rn(D, __fadd_rn(s.q2, s.p2));
    float sp = (__fadd_rn(y, __fmul_rn(CR, s.q2)) >= 10.0f) ? 1.0f : 0.0f;
    s.p2 = __fadd_rn(__fmul_rn(D, s.p2), sp);
    return sp;
}

__device__ __forceinline__ void cp_async4(void* sm, const void* gm) {
    unsigned s = (unsigned)__cvta_generic_to_shared(sm);
    asm volatile("cp.async.ca.shared.global [%0], [%1], 4;" :: "r"(s), "l"(gm));
}
__device__ __forceinline__ void cp_commit() { asm volatile("cp.async.commit_group;"); }
__device__ __forceinline__ void cp_wait0()  { asm volatile("cp.async.wait_group 0;" ::: "memory"); }

// ---------------------------------------------------------------------------
// K0: 4x4 sum-pool (gain 11) + transpose (B,2,128,128,T) -> t-major g_s0.
// ---------------------------------------------------------------------------
__global__ void pool0_transpose_kernel(const float* __restrict__ x) {
    __shared__ float sm[32][33];
    const int tx = threadIdx.x, ty = threadIdx.y;
    const int tb = blockIdx.x, nb = blockIdx.y;
    const int t  = tb * 32 + tx;
    const int ho = nb & 31;
    const int bc = nb >> 5;
    for (int j = ty; j < 32; j += 8) {
        float acc = 0.f;
        if (t < T_STEPS) {
            #pragma unroll
            for (int dy = 0; dy < 4; ++dy) {
                int h = ho * 4 + dy;
                const float* rowp = x + ((bc * 128 + h) * 128 + j * 4) * T_STEPS + t;
                acc += rowp[0] + rowp[300] + rowp[600] + rowp[900];
            }
        }
        sm[j][tx] = 11.0f * acc;
    }
    __syncthreads();
    for (int jj = ty; jj < 32; jj += 8) {
        int t2 = tb * 32 + jj;
        if (t2 < T_STEPS)
            g_s0[t2 * 16384 + nb * 32 + tx] = sm[tx][jj];
    }
}

// ---- generic in-place psp+spike scan ---------------------------------------
__device__ __forceinline__ void scan_body(float* buf, int N) {
    int n = blockIdx.x * blockDim.x + threadIdx.x;
    if (n >= N) return;
    Srm st = {0.f, 0.f, 0.f, 0.f};
    #pragma unroll 1
    for (int t = 0; t < T_STEPS; ++t) {
        float u = buf[t * N + n];
        buf[t * N + n] = srm_step(st, u);
    }
}
__global__ void scan_s0_kernel() { scan_body(g_s0, 16384); }
__global__ void scan_u5_kernel() { scan_body(g_u5, 4096); }

// ---------------------------------------------------------------------------
// conv1 (5x5,pad2,2->16) + psp+spike + 2x2 pool + psp+spike, fused.
// grid (hp=16, b=8), 512 thr. Lane layout: xp = lane[0:3], kh = lane[4]
// (each LDS half-warp phase holds a single kh -> conflict-free); co = warp id.
// kh halves combined with shfl_xor(16).
// ---------------------------------------------------------------------------
__global__ void __launch_bounds__(512) conv1_fused_kernel(const float* __restrict__ W1) {
    __shared__ float sbuf[2][432];        // [buf][ci*216 + r*36 + c], rows 2hp-2..2hp+3
    const int tid = threadIdx.x;
    const int xp  = tid & 15;
    const int kh  = (tid >> 4) & 1;
    const int co  = tid >> 5;
    const int hp  = blockIdx.x;
    const int b   = blockIdx.y;
    float w[25];
    #pragma unroll
    for (int k = 0; k < 25; ++k) w[k] = W1[co * 50 + kh * 25 + k];
    for (int i = tid; i < 864; i += 512) ((float*)sbuf)[i] = 0.f;

    // precompute this thread's staging slot (1 elem, tid<432)
    bool sv = false; int gOff = 0;
    if (tid < 432) {
        int ci = tid / 216, rem = tid - ci * 216, r = rem / 36, c = rem - r * 36;
        int row = 2 * hp + r - 2, col = c - 2;
        if (row >= 0 && row < 32 && col >= 0 && col < 32) {
            sv = true;
            gOff = b * 2048 + ci * 1024 + row * 32 + col;
        }
    }
    __syncthreads();

    if (sv) cp_async4(&sbuf[0][tid], g_s0 + gOff);
    cp_commit(); cp_wait0();
    __syncthreads();

    Srm c00 = {0,0,0,0}, c01 = {0,0,0,0}, c10 = {0,0,0,0}, c11 = {0,0,0,0}, pl = {0,0,0,0};
    const int outIdx = ((b * 16 + co) * 16 + hp) * 16 + xp;

    #pragma unroll 1
    for (int t = 0; t < T_STEPS; ++t) {
        const int cur = t & 1;
        if (sv && t + 1 < T_STEPS)
            cp_async4(&sbuf[cur ^ 1][tid], g_s0 + (t + 1) * 16384 + gOff);
        cp_commit();

        float a00 = 0.f, a01 = 0.f, a10 = 0.f, a11 = 0.f;
        {
            const float* sp_ = &sbuf[cur][kh * 216 + 2 * xp];
            #pragma unroll
            for (int r = 0; r < 6; ++r) {
                float2 p0 = *(const float2*)(sp_ + r * 36);
                float2 p1 = *(const float2*)(sp_ + r * 36 + 2);
                float2 p2 = *(const float2*)(sp_ + r * 36 + 4);
                float v[6] = {p0.x, p0.y, p1.x, p1.y, p2.x, p2.y};
                if (r < 5) {                       // y0: ky = r
                    const int kb = r * 5;
                    #pragma unroll
                    for (int kx = 0; kx < 5; ++kx) {
                        a00 = fmaf(v[kx],     w[kb + kx], a00);
                        a01 = fmaf(v[kx + 1], w[kb + kx], a01);
                    }
                }
                if (r >= 1) {                      // y1: ky = r-1
                    const int kb = (r - 1) * 5;
                    #pragma unroll
                    for (int kx = 0; kx < 5; ++kx) {
                        a10 = fmaf(v[kx],     w[kb + kx], a10);
                        a11 = fmaf(v[kx + 1], w[kb + kx], a11);
                    }
                }
            }
        }
        // combine input-channel halves (kh0 + kh1), identical on both lanes
        a00 += __shfl_xor_sync(0xffffffffu, a00, 16);
        a01 += __shfl_xor_sync(0xffffffffu, a01, 16);
        a10 += __shfl_xor_sync(0xffffffffu, a10, 16);
        a11 += __shfl_xor_sync(0xffffffffu, a11, 16);

        float s00 = srm_step(c00, a00), s01 = srm_step(c01, a01);
        float s10 = srm_step(c10, a10), s11 = srm_step(c11, a11);
        float u = 11.0f * ((s00 + s01) + (s10 + s11));
        float sp = srm_step(pl, u);
        if (kh == 0) g_s2[t * 32768 + outIdx] = sp;

        cp_wait0();
        __syncthreads();
    }
}

// ---------------------------------------------------------------------------
// conv2 (3x3,pad1,16->32) + psp+spike + 2x2 pool + psp+spike, fused.
// grid (hp=8, b=8, xh=2), 512 thr. Lane layout: xp = lane[0:1], kq = lane[2:3],
// co_lo = lane[4]; co = tid>>4. Smem channel stride padded to 42 floats so
// kq quarters map to banks {0,8,16,24}: LDS.64 conflict-free, co broadcasts.
// kq quarters combined with shfl_xor(4), shfl_xor(8).
// ---------------------------------------------------------------------------
#define C2_CS 42                           // padded channel stride (floats)
__global__ void __launch_bounds__(512) conv2_fused_kernel(const float* __restrict__ W2) {
    __shared__ float sbuf[2][16 * C2_CS];  // [buf][ci*42 + r*10 + c], rows 2hp-1..2hp+2
    const int tid = threadIdx.x;
    const int xp  = tid & 3;
    const int kq  = (tid >> 2) & 3;
    const int co  = tid >> 4;             // 0..31
    const int hp  = blockIdx.x;           // 0..7
    const int b   = blockIdx.y;
    const int xh  = blockIdx.z;           // 0..1
    float w[36];
    #pragma unroll
    for (int k = 0; k < 36; ++k) w[k] = W2[co * 144 + kq * 36 + k];
    for (int i = tid; i < 2 * 16 * C2_CS; i += 512) ((float*)sbuf)[i] = 0.f;

    // precompute staging slots (padded layout): elems tid and tid+512 (< 672)
    bool sv0 = false, sv1 = false; int g0 = 0, g1 = 0;
    {
        int i = tid;
        int ci = i / C2_CS, rem = i - ci * C2_CS;
        if (rem < 40) {
            int r = rem / 10, c = rem - r * 10;
            int row = 2 * hp + r - 1, col = xh * 8 + c - 1;
            if (row >= 0 && row < 16 && col >= 0 && col < 16) {
                sv0 = true; g0 = b * 4096 + ci * 256 + row * 16 + col;
            }
        }
    }
    if (tid + 512 < 16 * C2_CS) {
        int i = tid + 512;
        int ci = i / C2_CS, rem = i - ci * C2_CS;
        if (rem < 40) {
            int r = rem / 10, c = rem - r * 10;
            int row = 2 * hp + r - 1, col = xh * 8 + c - 1;
            if (row >= 0 && row < 16 && col >= 0 && col < 16) {
                sv1 = true; g1 = b * 4096 + ci * 256 + row * 16 + col;
            }
        }
    }
    __syncthreads();

    if (sv0) cp_async4(&sbuf[0][tid],       g_s2 + g0);
    if (sv1) cp_async4(&sbuf[0][tid + 512], g_s2 + g1);
    cp_commit(); cp_wait0();
    __syncthreads();

    Srm c00 = {0,0,0,0}, c01 = {0,0,0,0}, c10 = {0,0,0,0}, c11 = {0,0,0,0}, pl = {0,0,0,0};
    const int outIdx = ((b * 32 + co) * 8 + hp) * 8 + xh * 4 + xp;

    #pragma unroll 1
    for (int t = 0; t < T_STEPS; ++t) {
        const int cur = t & 1;
        if (t + 1 < T_STEPS) {
            const float* fr = g_s2 + (t + 1) * 32768;
            if (sv0) cp_async4(&sbuf[cur ^ 1][tid],       fr + g0);
            if (sv1) cp_async4(&sbuf[cur ^ 1][tid + 512], fr + g1);
        }
        cp_commit();

        float a00 = 0.f, a01 = 0.f, a10 = 0.f, a11 = 0.f;
        #pragma unroll
        for (int lci = 0; lci < 4; ++lci) {
            const float* sp_ = &sbuf[cur][(kq * 4 + lci) * C2_CS + 2 * xp];
            #pragma unroll
            for (int r = 0; r < 4; ++r) {
                float2 p0 = *(const float2*)(sp_ + r * 10);
                float2 p1 = *(const float2*)(sp_ + r * 10 + 2);
                float v[4] = {p0.x, p0.y, p1.x, p1.y};
                if (r < 3) {                       // y0: ky = r
                    const int kb = lci * 9 + r * 3;
                    #pragma unroll
                    for (int kx = 0; kx < 3; ++kx) {
                        a00 = fmaf(v[kx],     w[kb + kx], a00);
                        a01 = fmaf(v[kx + 1], w[kb + kx], a01);
                    }
                }
                if (r >= 1) {                      // y1: ky = r-1
                    const int kb = lci * 9 + (r - 1) * 3;
                    #pragma unroll
                    for (int kx = 0; kx < 3; ++kx) {
                        a10 = fmaf(v[kx],     w[kb + kx], a10);
                        a11 = fmaf(v[kx + 1], w[kb + kx], a11);
                    }
                }
            }
        }
        // combine quarters: ((q0+q1)+(q2+q3)), identical on all 4 lanes
        a00 += __shfl_xor_sync(0xffffffffu, a00, 4);
        a01 += __shfl_xor_sync(0xffffffffu, a01, 4);
        a10 += __shfl_xor_sync(0xffffffffu, a10, 4);
        a11 += __shfl_xor_sync(0xffffffffu, a11, 4);
        a00 += __shfl_xor_sync(0xffffffffu, a00, 8);
        a01 += __shfl_xor_sync(0xffffffffu, a01, 8);
        a10 += __shfl_xor_sync(0xffffffffu, a10, 8);
        a11 += __shfl_xor_sync(0xffffffffu, a11, 8);

        float s00 = srm_step(c00, a00), s01 = srm_step(c01, a01);
        float s10 = srm_step(c10, a10), s11 = srm_step(c11, a11);
        float u = 11.0f * ((s00 + s01) + (s10 + s11));
        float sp = srm_step(pl, u);
        if (kq == 0) g_s4[t * 16384 + outIdx] = sp;

        cp_wait0();
        __syncthreads();
    }
}

// ---------------------------------------------------------------------------
// fc1 GEMM: rows=(t,b) 2400, K=2048, N=512. 64x64 tile, 4x4 micro, kc=32,
// register double-buffered global loads, LDS.128 inner loop. 304 blocks.
// ---------------------------------------------------------------------------
__global__ void __launch_bounds__(256) fc1_gemm_kernel(const float* __restrict__ Wf1) {
    __shared__ float As[32 * 68];
    __shared__ float Bs[32 * 68];
    const int tid = threadIdx.x;
    const int txn = tid & 15, tym = tid >> 4;
    const int m0 = blockIdx.x * 64, n0 = blockIdx.y * 64;
    float acc[4][4];
    #pragma unroll
    for (int i = 0; i < 4; ++i)
        #pragma unroll
        for (int j = 0; j < 4; ++j) acc[i][j] = 0.f;

    float4 ra[2], rb[2];
    #pragma unroll
    for (int e = 0; e < 2; ++e) {
        int i = tid + e * 256, m = i >> 3, kq = i & 7, row = m0 + m;
        ra[e] = (row < 2400) ? *(const float4*)(g_s4 + row * 2048 + kq * 4)
                             : make_float4(0.f, 0.f, 0.f, 0.f);
        rb[e] = *(const float4*)(Wf1 + (n0 + m) * 2048 + kq * 4);
    }

    for (int kb = 0; kb < 2048; kb += 32) {
        #pragma unroll
        for (int e = 0; e < 2; ++e) {
            int i = tid + e * 256, m = i >> 3, kq = i & 7;
            As[(kq * 4 + 0) * 68 + m] = ra[e].x;
            As[(kq * 4 + 1) * 68 + m] = ra[e].y;
            As[(kq * 4 + 2) * 68 + m] = ra[e].z;
            As[(kq * 4 + 3) * 68 + m] = ra[e].w;
            Bs[(kq * 4 + 0) * 68 + m] = rb[e].x;
            Bs[(kq * 4 + 1) * 68 + m] = rb[e].y;
            Bs[(kq * 4 + 2) * 68 + m] = rb[e].z;
            Bs[(kq * 4 + 3) * 68 + m] = rb[e].w;
        }
        __syncthreads();
        if (kb + 32 < 2048) {
            #pragma unroll
            for (int e = 0; e < 2; ++e) {
                int i = tid + e * 256, m = i >> 3, kq = i & 7, row = m0 + m;
                ra[e] = (row < 2400) ? *(const float4*)(g_s4 + row * 2048 + kb + 32 + kq * 4)
                                     : make_float4(0.f, 0.f, 0.f, 0.f);
                rb[e] = *(const float4*)(Wf1 + (n0 + m) * 2048 + kb + 32 + kq * 4);
            }
        }
        #pragma unroll
        for (int k = 0; k < 32; ++k) {
            float4 aq = *(const float4*)&As[k * 68 + tym * 4];
            float4 bq = *(const float4*)&Bs[k * 68 + txn * 4];
            float av[4] = {aq.x, aq.y, aq.z, aq.w};
            float bv[4] = {bq.x, bq.y, bq.z, bq.w};
            #pragma unroll
            for (int i = 0; i < 4; ++i)
                #pragma unroll
                for (int j = 0; j < 4; ++j)
                    acc[i][j] = fmaf(av[i], bv[j], acc[i][j]);
        }
        __syncthreads();
    }
    #pragma unroll
    for (int i = 0; i < 4; ++i) {
        int row = m0 + tym * 4 + i;
        if (row < 2400) {
            float4 v = make_float4(acc[i][0], acc[i][1], acc[i][2], acc[i][3]);
            *(float4*)(g_u5 + row * 512 + n0 + txn * 4) = v;
        }
    }
}

// ---------------------------------------------------------------------------
__global__ void fc2_kernel(const float* __restrict__ Wf2) {
    int idx = blockIdx.x * 256 + threadIdx.x;
    if (idx >= 2400 * 11) return;
    int row = idx / 11, o = idx % 11;
    const float* a  = g_u5 + row * 512;
    const float* wv = Wf2 + o * 512;
    float acc = 0.f;
    #pragma unroll 8
    for (int c = 0; c < 512; ++c) acc = fmaf(a[c], wv[c], acc);
    g_u6[idx] = acc;
}

__global__ void final_scan_kernel(float* __restrict__ out) {
    int n = threadIdx.x;
    if (n >= 88) return;
    Srm st = {0.f, 0.f, 0.f, 0.f};
    #pragma unroll 1
    for (int t = 0; t < T_STEPS; ++t) {
        float s = srm_step(st, g_u6[t * 88 + n]);
        out[n * 300 + t] = s;
    }
}

// ---------------------------------------------------------------------------
extern "C" void kernel_launch(void* const* d_in, const int* in_sizes, int n_in,
                              void* d_out, int out_size) {
    (void)in_sizes; (void)n_in; (void)out_size;
    const float* s_in = (const float*)d_in[0];
    const float* W1   = (const float*)d_in[1];
    const float* W2   = (const float*)d_in[2];
    const float* Wf1  = (const float*)d_in[3];
    const float* Wf2  = (const float*)d_in[4];
    float* out = (float*)d_out;

    pool0_transpose_kernel<<<dim3(10, 512), dim3(32, 8)>>>(s_in);
    scan_s0_kernel<<<128, 128>>>();
    conv1_fused_kernel<<<dim3(16, 8), 512>>>(W1);
    conv2_fused_kernel<<<dim3(8, 8, 2), 512>>>(W2);
    fc1_gemm_kernel<<<dim3(38, 8), 256>>>(Wf1);
    scan_u5_kernel<<<32, 128>>>();
    fc2_kernel<<<104, 256>>>(Wf2);
    final_scan_kernel<<<1, 128>>>(out);
}

// round 7
// speedup vs baseline: 1.5658x; 1.0075x over previous
#include <cuda_runtime.h>

// ---------------------------------------------------------------------------
// SLAYER SRM-alpha SNN forward, t-major layout [t*N + n].
// R6: conv inner products use packed fp32x2 FFMA2 (x-paired quads share
// weights); SRM scan states packed as f32x2 (separate mul/add rounding kept
// -> bit-exact vs scalar). Layout/staging identical to R5 (bank-conflict-free).
// ---------------------------------------------------------------------------

#define T_STEPS 300

__device__ float g_s0[16384 * T_STEPS];   // pool0 potentials -> spikes (B,2,32,32)
__device__ float g_s2[32768 * T_STEPS];   // pool1 spikes (B,16,16,16)
__device__ float g_s4[16384 * T_STEPS];   // pool2 spikes (B,32,8,8)
__device__ float g_u5[4096  * T_STEPS];   // fc1 potentials -> spikes in place
__device__ float g_u6[88    * T_STEPS];   // fc2 potentials

typedef unsigned long long u64_t;

// ---- fp32x2 packed helpers --------------------------------------------------
__device__ __forceinline__ u64_t pk2(float lo, float hi) {
    u64_t r; asm("mov.b64 %0,{%1,%2};" : "=l"(r) : "f"(lo), "f"(hi)); return r;
}
__device__ __forceinline__ u64_t dup2(float x) {
    u64_t r; asm("mov.b64 %0,{%1,%1};" : "=l"(r) : "f"(x)); return r;
}
__device__ __forceinline__ void upk2(u64_t v, float& lo, float& hi) {
    asm("mov.b64 {%0,%1},%2;" : "=f"(lo), "=f"(hi) : "l"(v));
}
__device__ __forceinline__ u64_t fma2(u64_t a, u64_t b, u64_t c) {
    u64_t d; asm("fma.rn.f32x2 %0,%1,%2,%3;" : "=l"(d) : "l"(a), "l"(b), "l"(c)); return d;
}
__device__ __forceinline__ u64_t mul2(u64_t a, u64_t b) {
    u64_t d; asm("mul.rn.f32x2 %0,%1,%2;" : "=l"(d) : "l"(a), "l"(b)); return d;
}
__device__ __forceinline__ u64_t add2(u64_t a, u64_t b) {
    u64_t d; asm("add.rn.f32x2 %0,%1,%2;" : "=l"(d) : "l"(a), "l"(b)); return d;
}

// ---- SRM constants ----------------------------------------------------------
#define SRM_D  0.36787944117144233f   // exp(-1)
#define SRM_CE 2.7182818284590452f    // e
#define SRM_CR -54.365636569180905f   // -2*theta*e

struct Srm { float p1, q1, p2, q2; };

__device__ __forceinline__ float srm_step(Srm& s, float u) {
    s.q1 = __fmul_rn(SRM_D, __fadd_rn(s.q1, s.p1));
    s.p1 = __fadd_rn(__fmul_rn(SRM_D, s.p1), u);
    float y = __fmul_rn(SRM_CE, s.q1);
    s.q2 = __fmul_rn(SRM_D, __fadd_rn(s.q2, s.p2));
    float sp = (__fadd_rn(y, __fmul_rn(SRM_CR, s.q2)) >= 10.0f) ? 1.0f : 0.0f;
    s.p2 = __fadd_rn(__fmul_rn(SRM_D, s.p2), sp);
    return sp;
}

// packed pair of independent SRM neurons; mul/add kept separate (no fma) so
// each lane is bit-identical to the scalar srm_step.
struct Srm2 { u64_t p1, q1, p2, q2; };

__device__ __forceinline__ void srm2_step(Srm2& s, u64_t u, float& slo, float& shi) {
    const u64_t D2  = dup2(SRM_D);
    const u64_t CE2 = dup2(SRM_CE);
    const u64_t CR2 = dup2(SRM_CR);
    s.q1 = mul2(D2, add2(s.q1, s.p1));
    s.p1 = add2(mul2(D2, s.p1), u);
    u64_t y = mul2(CE2, s.q1);
    s.q2 = mul2(D2, add2(s.q2, s.p2));
    u64_t m = add2(y, mul2(CR2, s.q2));
    float mlo, mhi; upk2(m, mlo, mhi);
    slo = (mlo >= 10.0f) ? 1.0f : 0.0f;
    shi = (mhi >= 10.0f) ? 1.0f : 0.0f;
    s.p2 = add2(mul2(D2, s.p2), pk2(slo, shi));
}

__device__ __forceinline__ void cp_async4(void* sm, const void* gm) {
    unsigned s = (unsigned)__cvta_generic_to_shared(sm);
    asm volatile("cp.async.ca.shared.global [%0], [%1], 4;" :: "r"(s), "l"(gm));
}
__device__ __forceinline__ void cp_commit() { asm volatile("cp.async.commit_group;"); }
__device__ __forceinline__ void cp_wait0()  { asm volatile("cp.async.wait_group 0;" ::: "memory"); }

// ---------------------------------------------------------------------------
// K0: 4x4 sum-pool (gain 11) + transpose (B,2,128,128,T) -> t-major g_s0.
// ---------------------------------------------------------------------------
__global__ void pool0_transpose_kernel(const float* __restrict__ x) {
    __shared__ float sm[32][33];
    const int tx = threadIdx.x, ty = threadIdx.y;
    const int tb = blockIdx.x, nb = blockIdx.y;
    const int t  = tb * 32 + tx;
    const int ho = nb & 31;
    const int bc = nb >> 5;
    for (int j = ty; j < 32; j += 8) {
        float acc = 0.f;
        if (t < T_STEPS) {
            #pragma unroll
            for (int dy = 0; dy < 4; ++dy) {
                int h = ho * 4 + dy;
                const float* rowp = x + ((bc * 128 + h) * 128 + j * 4) * T_STEPS + t;
                acc += rowp[0] + rowp[300] + rowp[600] + rowp[900];
            }
        }
        sm[j][tx] = 11.0f * acc;
    }
    __syncthreads();
    for (int jj = ty; jj < 32; jj += 8) {
        int t2 = tb * 32 + jj;
        if (t2 < T_STEPS)
            g_s0[t2 * 16384 + nb * 32 + tx] = sm[tx][jj];
    }
}

// ---- generic in-place psp+spike scan ---------------------------------------
__device__ __forceinline__ void scan_body(float* buf, int N) {
    int n = blockIdx.x * blockDim.x + threadIdx.x;
    if (n >= N) return;
    Srm st = {0.f, 0.f, 0.f, 0.f};
    #pragma unroll 1
    for (int t = 0; t < T_STEPS; ++t) {
        float u = buf[t * N + n];
        buf[t * N + n] = srm_step(st, u);
    }
}
__global__ void scan_s0_kernel() { scan_body(g_s0, 16384); }
__global__ void scan_u5_kernel() { scan_body(g_u5, 4096); }

// ---------------------------------------------------------------------------
// conv1 (5x5,pad2,2->16) + psp+spike + 2x2 pool + psp+spike, fused.
// grid (hp=16, b=8), 512 thr. xp = lane[0:3], kh = lane[4], co = warp id.
// Quads x-packed as f32x2: acc0=(a00,a01), acc1=(a10,a11); weights dup-paired.
// kh halves combined with shfl_xor(16).
// ---------------------------------------------------------------------------
__global__ void __launch_bounds__(512) conv1_fused_kernel(const float* __restrict__ W1) {
    __shared__ float sbuf[2][432];        // [buf][ci*216 + r*36 + c], rows 2hp-2..2hp+3
    const int tid = threadIdx.x;
    const int xp  = tid & 15;
    const int kh  = (tid >> 4) & 1;
    const int co  = tid >> 5;
    const int hp  = blockIdx.x;
    const int b   = blockIdx.y;
    u64_t wd[25];
    #pragma unroll
    for (int k = 0; k < 25; ++k) wd[k] = dup2(W1[co * 50 + kh * 25 + k]);
    for (int i = tid; i < 864; i += 512) ((float*)sbuf)[i] = 0.f;

    bool sv = false; int gOff = 0;
    if (tid < 432) {
        int ci = tid / 216, rem = tid - ci * 216, r = rem / 36, c = rem - r * 36;
        int row = 2 * hp + r - 2, col = c - 2;
        if (row >= 0 && row < 32 && col >= 0 && col < 32) {
            sv = true;
            gOff = b * 2048 + ci * 1024 + row * 32 + col;
        }
    }
    __syncthreads();

    if (sv) cp_async4(&sbuf[0][tid], g_s0 + gOff);
    cp_commit(); cp_wait0();
    __syncthreads();

    Srm2 cA = {0,0,0,0}, cB = {0,0,0,0};
    Srm   pl = {0.f,0.f,0.f,0.f};
    const int outIdx = ((b * 16 + co) * 16 + hp) * 16 + xp;

    #pragma unroll 1
    for (int t = 0; t < T_STEPS; ++t) {
        const int cur = t & 1;
        if (sv && t + 1 < T_STEPS)
            cp_async4(&sbuf[cur ^ 1][tid], g_s0 + (t + 1) * 16384 + gOff);
        cp_commit();

        u64_t acc0 = 0ull, acc1 = 0ull;   // (a00,a01), (a10,a11)
        {
            const float* sp_ = &sbuf[cur][kh * 216 + 2 * xp];
            #pragma unroll
            for (int r = 0; r < 6; ++r) {
                float2 f0 = *(const float2*)(sp_ + r * 36);
                float2 f1 = *(const float2*)(sp_ + r * 36 + 2);
                float2 f2 = *(const float2*)(sp_ + r * 36 + 4);
                u64_t vp[5];
                vp[0] = pk2(f0.x, f0.y);
                vp[1] = pk2(f0.y, f1.x);
                vp[2] = pk2(f1.x, f1.y);
                vp[3] = pk2(f1.y, f2.x);
                vp[4] = pk2(f2.x, f2.y);
                if (r < 5) {                       // y0: ky = r
                    #pragma unroll
                    for (int kx = 0; kx < 5; ++kx)
                        acc0 = fma2(vp[kx], wd[r * 5 + kx], acc0);
                }
                if (r >= 1) {                      // y1: ky = r-1
                    #pragma unroll
                    for (int kx = 0; kx < 5; ++kx)
                        acc1 = fma2(vp[kx], wd[(r - 1) * 5 + kx], acc1);
                }
            }
        }
        // combine input-channel halves (commutative add -> lanes identical)
        acc0 = add2(acc0, __shfl_xor_sync(0xffffffffu, acc0, 16));
        acc1 = add2(acc1, __shfl_xor_sync(0xffffffffu, acc1, 16));

        float s00, s01, s10, s11;
        srm2_step(cA, acc0, s00, s01);
        srm2_step(cB, acc1, s10, s11);
        float u = 11.0f * ((s00 + s01) + (s10 + s11));   // exact small ints
        float sp = srm_step(pl, u);
        if (kh == 0) g_s2[t * 32768 + outIdx] = sp;

        cp_wait0();
        __syncthreads();
    }
}

// ---------------------------------------------------------------------------
// conv2 (3x3,pad1,16->32) + psp+spike + 2x2 pool + psp+spike, fused.
// grid (hp=8, b=8, xh=2), 512 thr. xp = lane[0:1], kq = lane[2:3],
// co_lo = lane[4]; co = tid>>4. Channel stride padded to 42 floats
// (kq quarters -> banks {0,8,16,24}: LDS.64 conflict-free).
// Quads x-packed f32x2; kq quarters combined with shfl_xor(4),(8).
// ---------------------------------------------------------------------------
#define C2_CS 42                           // padded channel stride (floats)
__global__ void __launch_bounds__(512) conv2_fused_kernel(const float* __restrict__ W2) {
    __shared__ float sbuf[2][16 * C2_CS];  // [buf][ci*42 + r*10 + c], rows 2hp-1..2hp+2
    const int tid = threadIdx.x;
    const int xp  = tid & 3;
    const int kq  = (tid >> 2) & 3;
    const int co  = tid >> 4;             // 0..31
    const int hp  = blockIdx.x;           // 0..7
    const int b   = blockIdx.y;
    const int xh  = blockIdx.z;           // 0..1
    u64_t wd[36];
    #pragma unroll
    for (int k = 0; k < 36; ++k) wd[k] = dup2(W2[co * 144 + kq * 36 + k]);
    for (int i = tid; i < 2 * 16 * C2_CS; i += 512) ((float*)sbuf)[i] = 0.f;

    bool sv0 = false, sv1 = false; int g0 = 0, g1 = 0;
    {
        int i = tid;
        int ci = i / C2_CS, rem = i - ci * C2_CS;
        if (rem < 40) {
            int r = rem / 10, c = rem - r * 10;
            int row = 2 * hp + r - 1, col = xh * 8 + c - 1;
            if (row >= 0 && row < 16 && col >= 0 && col < 16) {
                sv0 = true; g0 = b * 4096 + ci * 256 + row * 16 + col;
            }
        }
    }
    if (tid + 512 < 16 * C2_CS) {
        int i = tid + 512;
        int ci = i / C2_CS, rem = i - ci * C2_CS;
        if (rem < 40) {
            int r = rem / 10, c = rem - r * 10;
            int row = 2 * hp + r - 1, col = xh * 8 + c - 1;
            if (row >= 0 && row < 16 && col >= 0 && col < 16) {
                sv1 = true; g1 = b * 4096 + ci * 256 + row * 16 + col;
            }
        }
    }
    __syncthreads();

    if (sv0) cp_async4(&sbuf[0][tid],       g_s2 + g0);
    if (sv1) cp_async4(&sbuf[0][tid + 512], g_s2 + g1);
    cp_commit(); cp_wait0();
    __syncthreads();

    Srm2 cA = {0,0,0,0}, cB = {0,0,0,0};
    Srm   pl = {0.f,0.f,0.f,0.f};
    const int outIdx = ((b * 32 + co) * 8 + hp) * 8 + xh * 4 + xp;

    #pragma unroll 1
    for (int t = 0; t < T_STEPS; ++t) {
        const int cur = t & 1;
        if (t + 1 < T_STEPS) {
            const float* fr = g_s2 + (t + 1) * 32768;
            if (sv0) cp_async4(&sbuf[cur ^ 1][tid],       fr + g0);
            if (sv1) cp_async4(&sbuf[cur ^ 1][tid + 512], fr + g1);
        }
        cp_commit();

        u64_t acc0 = 0ull, acc1 = 0ull;   // (a00,a01), (a10,a11)
        #pragma unroll
        for (int lci = 0; lci < 4; ++lci) {
            const float* sp_ = &sbuf[cur][(kq * 4 + lci) * C2_CS + 2 * xp];
            #pragma unroll
            for (int r = 0; r < 4; ++r) {
                float2 f0 = *(const float2*)(sp_ + r * 10);
                float2 f1 = *(const float2*)(sp_ + r * 10 + 2);
                u64_t vp[3];
                vp[0] = pk2(f0.x, f0.y);
                vp[1] = pk2(f0.y, f1.x);
                vp[2] = pk2(f1.x, f1.y);
                if (r < 3) {                       // y0: ky = r
                    #pragma unroll
                    for (int kx = 0; kx < 3; ++kx)
                        acc0 = fma2(vp[kx], wd[lci * 9 + r * 3 + kx], acc0);
                }
                if (r >= 1) {                      // y1: ky = r-1
                    #pragma unroll
                    for (int kx = 0; kx < 3; ++kx)
                        acc1 = fma2(vp[kx], wd[lci * 9 + (r - 1) * 3 + kx], acc1);
                }
            }
        }
        // combine quarters: ((q0+q1)+(q2+q3)), identical on all 4 lanes
        acc0 = add2(acc0, __shfl_xor_sync(0xffffffffu, acc0, 4));
        acc1 = add2(acc1, __shfl_xor_sync(0xffffffffu, acc1, 4));
        acc0 = add2(acc0, __shfl_xor_sync(0xffffffffu, acc0, 8));
        acc1 = add2(acc1, __shfl_xor_sync(0xffffffffu, acc1, 8));

        float s00, s01, s10, s11;
        srm2_step(cA, acc0, s00, s01);
        srm2_step(cB, acc1, s10, s11);
        float u = 11.0f * ((s00 + s01) + (s10 + s11));
        float sp = srm_step(pl, u);
        if (kq == 0) g_s4[t * 16384 + outIdx] = sp;

        cp_wait0();
        __syncthreads();
    }
}

// ---------------------------------------------------------------------------
// fc1 GEMM: rows=(t,b) 2400, K=2048, N=512. 64x64 tile, 4x4 micro, kc=32,
// register double-buffered global loads, LDS.128 inner loop. 304 blocks.
// ---------------------------------------------------------------------------
__global__ void __launch_bounds__(256) fc1_gemm_kernel(const float* __restrict__ Wf1) {
    __shared__ float As[32 * 68];
    __shared__ float Bs[32 * 68];
    const int tid = threadIdx.x;
    const int txn = tid & 15, tym = tid >> 4;
    const int m0 = blockIdx.x * 64, n0 = blockIdx.y * 64;
    float acc[4][4];
    #pragma unroll
    for (int i = 0; i < 4; ++i)
        #pragma unroll
        for (int j = 0; j < 4; ++j) acc[i][j] = 0.f;

    float4 ra[2], rb[2];
    #pragma unroll
    for (int e = 0; e < 2; ++e) {
        int i = tid + e * 256, m = i >> 3, kq = i & 7, row = m0 + m;
        ra[e] = (row < 2400) ? *(const float4*)(g_s4 + row * 2048 + kq * 4)
                             : make_float4(0.f, 0.f, 0.f, 0.f);
        rb[e] = *(const float4*)(Wf1 + (n0 + m) * 2048 + kq * 4);
    }

    for (int kb = 0; kb < 2048; kb += 32) {
        #pragma unroll
        for (int e = 0; e < 2; ++e) {
            int i = tid + e * 256, m = i >> 3, kq = i & 7;
            As[(kq * 4 + 0) * 68 + m] = ra[e].x;
            As[(kq * 4 + 1) * 68 + m] = ra[e].y;
            As[(kq * 4 + 2) * 68 + m] = ra[e].z;
            As[(kq * 4 + 3) * 68 + m] = ra[e].w;
            Bs[(kq * 4 + 0) * 68 + m] = rb[e].x;
            Bs[(kq * 4 + 1) * 68 + m] = rb[e].y;
            Bs[(kq * 4 + 2) * 68 + m] = rb[e].z;
            Bs[(kq * 4 + 3) * 68 + m] = rb[e].w;
        }
        __syncthreads();
        if (kb + 32 < 2048) {
            #pragma unroll
            for (int e = 0; e < 2; ++e) {
                int i = tid + e * 256, m = i >> 3, kq = i & 7, row = m0 + m;
                ra[e] = (row < 2400) ? *(const float4*)(g_s4 + row * 2048 + kb + 32 + kq * 4)
                                     : make_float4(0.f, 0.f, 0.f, 0.f);
                rb[e] = *(const float4*)(Wf1 + (n0 + m) * 2048 + kb + 32 + kq * 4);
            }
        }
        #pragma unroll
        for (int k = 0; k < 32; ++k) {
            float4 aq = *(const float4*)&As[k * 68 + tym * 4];
            float4 bq = *(const float4*)&Bs[k * 68 + txn * 4];
            float av[4] = {aq.x, aq.y, aq.z, aq.w};
            float bv[4] = {bq.x, bq.y, bq.z, bq.w};
            #pragma unroll
            for (int i = 0; i < 4; ++i)
                #pragma unroll
                for (int j = 0; j < 4; ++j)
                    acc[i][j] = fmaf(av[i], bv[j], acc[i][j]);
        }
        __syncthreads();
    }
    #pragma unroll
    for (int i = 0; i < 4; ++i) {
        int row = m0 + tym * 4 + i;
        if (row < 2400) {
            float4 v = make_float4(acc[i][0], acc[i][1], acc[i][2], acc[i][3]);
            *(float4*)(g_u5 + row * 512 + n0 + txn * 4) = v;
        }
    }
}

// ---------------------------------------------------------------------------
__global__ void fc2_kernel(const float* __restrict__ Wf2) {
    int idx = blockIdx.x * 256 + threadIdx.x;
    if (idx >= 2400 * 11) return;
    int row = idx / 11, o = idx % 11;
    const float* a  = g_u5 + row * 512;
    const float* wv = Wf2 + o * 512;
    float acc = 0.f;
    #pragma unroll 8
    for (int c = 0; c < 512; ++c) acc = fmaf(a[c], wv[c], acc);
    g_u6[idx] = acc;
}

__global__ void final_scan_kernel(float* __restrict__ out) {
    int n = threadIdx.x;
    if (n >= 88) return;
    Srm st = {0.f, 0.f, 0.f, 0.f};
    #pragma unroll 1
    for (int t = 0; t < T_STEPS; ++t) {
        float s = srm_step(st, g_u6[t * 88 + n]);
        out[n * 300 + t] = s;
    }
}

// ---------------------------------------------------------------------------
extern "C" void kernel_launch(void* const* d_in, const int* in_sizes, int n_in,
                              void* d_out, int out_size) {
    (void)in_sizes; (void)n_in; (void)out_size;
    const float* s_in = (const float*)d_in[0];
    const float* W1   = (const float*)d_in[1];
    const float* W2   = (const float*)d_in[2];
    const float* Wf1  = (const float*)d_in[3];
    const float* Wf2  = (const float*)d_in[4];
    float* out = (float*)d_out;

    pool0_transpose_kernel<<<dim3(10, 512), dim3(32, 8)>>>(s_in);
    scan_s0_kernel<<<128, 128>>>();
    conv1_fused_kernel<<<dim3(16, 8), 512>>>(W1);
    conv2_fused_kernel<<<dim3(8, 8, 2), 512>>>(W2);
    fc1_gemm_kernel<<<dim3(38, 8), 256>>>(Wf1);
    scan_u5_kernel<<<32, 128>>>();
    fc2_kernel<<<104, 256>>>(Wf2);
    final_scan_kernel<<<1, 128>>>(out);
}

// round 8
// speedup vs baseline: 1.6264x; 1.0387x over previous
#include <cuda_runtime.h>

// ---------------------------------------------------------------------------
// SLAYER SRM-alpha SNN forward, t-major layout [t*N + n].
// R7: conv kernels channel-packed (each thread computes 2 output channels via
// f32x2 with weight-pairs), halving LDS bytes per output; pool0 vectorized
// (float4 along t) with smem transpose. Scan arithmetic bit-identical.
// ---------------------------------------------------------------------------

#define T_STEPS 300

__device__ float g_s0[16384 * T_STEPS];   // pool0 potentials -> spikes (B,2,32,32)
__device__ float g_s2[32768 * T_STEPS];   // pool1 spikes (B,16,16,16)
__device__ float g_s4[16384 * T_STEPS];   // pool2 spikes (B,32,8,8)
__device__ float g_u5[4096  * T_STEPS];   // fc1 potentials -> spikes in place
__device__ float g_u6[88    * T_STEPS];   // fc2 potentials

typedef unsigned long long u64_t;

// ---- fp32x2 packed helpers --------------------------------------------------
__device__ __forceinline__ u64_t pk2(float lo, float hi) {
    u64_t r; asm("mov.b64 %0,{%1,%2};" : "=l"(r) : "f"(lo), "f"(hi)); return r;
}
__device__ __forceinline__ u64_t dup2(float x) {
    u64_t r; asm("mov.b64 %0,{%1,%1};" : "=l"(r) : "f"(x)); return r;
}
__device__ __forceinline__ void upk2(u64_t v, float& lo, float& hi) {
    asm("mov.b64 {%0,%1},%2;" : "=f"(lo), "=f"(hi) : "l"(v));
}
__device__ __forceinline__ u64_t fma2(u64_t a, u64_t b, u64_t c) {
    u64_t d; asm("fma.rn.f32x2 %0,%1,%2,%3;" : "=l"(d) : "l"(a), "l"(b), "l"(c)); return d;
}
__device__ __forceinline__ u64_t mul2(u64_t a, u64_t b) {
    u64_t d; asm("mul.rn.f32x2 %0,%1,%2;" : "=l"(d) : "l"(a), "l"(b)); return d;
}
__device__ __forceinline__ u64_t add2(u64_t a, u64_t b) {
    u64_t d; asm("add.rn.f32x2 %0,%1,%2;" : "=l"(d) : "l"(a), "l"(b)); return d;
}

// ---- SRM constants ----------------------------------------------------------
#define SRM_D  0.36787944117144233f   // exp(-1)
#define SRM_CE 2.7182818284590452f    // e
#define SRM_CR -54.365636569180905f   // -2*theta*e

struct Srm { float p1, q1, p2, q2; };

__device__ __forceinline__ float srm_step(Srm& s, float u) {
    s.q1 = __fmul_rn(SRM_D, __fadd_rn(s.q1, s.p1));
    s.p1 = __fadd_rn(__fmul_rn(SRM_D, s.p1), u);
    float y = __fmul_rn(SRM_CE, s.q1);
    s.q2 = __fmul_rn(SRM_D, __fadd_rn(s.q2, s.p2));
    float sp = (__fadd_rn(y, __fmul_rn(SRM_CR, s.q2)) >= 10.0f) ? 1.0f : 0.0f;
    s.p2 = __fadd_rn(__fmul_rn(SRM_D, s.p2), sp);
    return sp;
}

// packed pair of independent SRM neurons; mul/add kept separate (no fma) so
// each lane is bit-identical to the scalar srm_step.
struct Srm2 { u64_t p1, q1, p2, q2; };

__device__ __forceinline__ void srm2_step(Srm2& s, u64_t u, float& slo, float& shi) {
    const u64_t D2  = dup2(SRM_D);
    const u64_t CE2 = dup2(SRM_CE);
    const u64_t CR2 = dup2(SRM_CR);
    s.q1 = mul2(D2, add2(s.q1, s.p1));
    s.p1 = add2(mul2(D2, s.p1), u);
    u64_t y = mul2(CE2, s.q1);
    s.q2 = mul2(D2, add2(s.q2, s.p2));
    u64_t m = add2(y, mul2(CR2, s.q2));
    float mlo, mhi; upk2(m, mlo, mhi);
    slo = (mlo >= 10.0f) ? 1.0f : 0.0f;
    shi = (mhi >= 10.0f) ? 1.0f : 0.0f;
    s.p2 = add2(mul2(D2, s.p2), pk2(slo, shi));
}

__device__ __forceinline__ void cp_async4(void* sm, const void* gm) {
    unsigned s = (unsigned)__cvta_generic_to_shared(sm);
    asm volatile("cp.async.ca.shared.global [%0], [%1], 4;" :: "r"(s), "l"(gm));
}
__device__ __forceinline__ void cp_commit() { asm volatile("cp.async.commit_group;"); }
__device__ __forceinline__ void cp_wait0()  { asm volatile("cp.async.wait_group 0;" ::: "memory"); }

// ---------------------------------------------------------------------------
// K0: 4x4 sum-pool (gain 11) + transpose (B,2,128,128,T) -> t-major g_s0.
// float4 along t (w-stride = 300 floats = 1200 B, 16B aligned). smem transpose.
// grid (3, 512), block (32,8). Sums are exact small ints -> order-free.
// ---------------------------------------------------------------------------
__global__ void pool0_transpose_kernel(const float* __restrict__ x) {
    __shared__ float sm[128][33];
    const int tx = threadIdx.x, ty = threadIdx.y;
    const int tb = blockIdx.x;            // 0..2 (t-quads 0..95, 75 valid)
    const int nb = blockIdx.y;            // (bc, ho)
    const int ho = nb & 31, bc = nb >> 5;
    const int tq = tb * 32 + tx;          // t-quad index
    if (tq < 75) {
        const float* base = x + (size_t)((bc * 128 + ho * 4) * 128) * 300 + tq * 4;
        for (int j = ty; j < 32; j += 8) {    // j = wo
            float ax = 0.f, ay = 0.f, az = 0.f, aw = 0.f;
            #pragma unroll
            for (int dy = 0; dy < 4; ++dy) {
                const float* rp = base + (size_t)(dy * 128 + j * 4) * 300;
                float4 v0 = *(const float4*)(rp);
                float4 v1 = *(const float4*)(rp + 300);
                float4 v2 = *(const float4*)(rp + 600);
                float4 v3 = *(const float4*)(rp + 900);
                ax += ((v0.x + v1.x) + v2.x) + v3.x;
                ay += ((v0.y + v1.y) + v2.y) + v3.y;
                az += ((v0.z + v1.z) + v2.z) + v3.z;
                aw += ((v0.w + v1.w) + v2.w) + v3.w;
            }
            sm[tx * 4 + 0][j] = 11.0f * ax;
            sm[tx * 4 + 1][j] = 11.0f * ay;
            sm[tx * 4 + 2][j] = 11.0f * az;
            sm[tx * 4 + 3][j] = 11.0f * aw;
        }
    }
    __syncthreads();
    for (int tt = ty; tt < 128; tt += 8) {
        int t2 = tb * 128 + tt;
        if (t2 < T_STEPS)
            g_s0[t2 * 16384 + nb * 32 + tx] = sm[tt][tx];
    }
}

// ---- generic in-place psp+spike scan ---------------------------------------
__device__ __forceinline__ void scan_body(float* buf, int N) {
    int n = blockIdx.x * blockDim.x + threadIdx.x;
    if (n >= N) return;
    Srm st = {0.f, 0.f, 0.f, 0.f};
    #pragma unroll 1
    for (int t = 0; t < T_STEPS; ++t) {
        float u = buf[t * N + n];
        buf[t * N + n] = srm_step(st, u);
    }
}
__global__ void scan_s0_kernel() { scan_body(g_s0, 16384); }
__global__ void scan_u5_kernel() { scan_body(g_u5, 4096); }

// ---------------------------------------------------------------------------
// conv1 (5x5,pad2,2->16) + psp+spike + 2x2 pool + psp+spike, fused.
// grid (hp=16, b=8), 256 thr: xp = tid[0:3], kh = tid[4], co = tid>>5 (0..7).
// Each thread computes channels co and co+8 (f32x2 channel-packed: weights
// packed pairs, input dup'd). kh halves combined with shfl_xor(16).
// ---------------------------------------------------------------------------
__global__ void __launch_bounds__(256) conv1_fused_kernel(const float* __restrict__ W1) {
    __shared__ float sbuf[2][432];        // [buf][ci*216 + r*36 + c], rows 2hp-2..2hp+3
    const int tid = threadIdx.x;
    const int xp  = tid & 15;
    const int kh  = (tid >> 4) & 1;
    const int co  = tid >> 5;             // 0..7 -> channels co, co+8
    const int hp  = blockIdx.x;
    const int b   = blockIdx.y;
    u64_t wp[25];
    #pragma unroll
    for (int k = 0; k < 25; ++k)
        wp[k] = pk2(W1[co * 50 + kh * 25 + k], W1[(co + 8) * 50 + kh * 25 + k]);
    for (int i = tid; i < 864; i += 256) ((float*)sbuf)[i] = 0.f;

    // staging: slots tid and tid+256 (432 total)
    bool sv0 = false, sv1 = false; int g0 = 0, g1 = 0;
    {
        int i = tid;
        int ci = i / 216, rem = i - ci * 216, r = rem / 36, c = rem - r * 36;
        int row = 2 * hp + r - 2, col = c - 2;
        if (row >= 0 && row < 32 && col >= 0 && col < 32) {
            sv0 = true; g0 = b * 2048 + ci * 1024 + row * 32 + col;
        }
    }
    if (tid + 256 < 432) {
        int i = tid + 256;
        int ci = i / 216, rem = i - ci * 216, r = rem / 36, c = rem - r * 36;
        int row = 2 * hp + r - 2, col = c - 2;
        if (row >= 0 && row < 32 && col >= 0 && col < 32) {
            sv1 = true; g1 = b * 2048 + ci * 1024 + row * 32 + col;
        }
    }
    __syncthreads();

    if (sv0) cp_async4(&sbuf[0][tid],       g_s0 + g0);
    if (sv1) cp_async4(&sbuf[0][tid + 256], g_s0 + g1);
    cp_commit(); cp_wait0();
    __syncthreads();

    Srm2 stA = {0,0,0,0}, stB = {0,0,0,0}, stC = {0,0,0,0}, stD = {0,0,0,0};
    Srm  pl0 = {0.f,0.f,0.f,0.f}, pl1 = {0.f,0.f,0.f,0.f};
    const int outIdx = ((b * 16 + co) * 16 + hp) * 16 + xp;   // ch1 at +2048

    #pragma unroll 1
    for (int t = 0; t < T_STEPS; ++t) {
        const int cur = t & 1;
        if (t + 1 < T_STEPS) {
            const float* fr = g_s0 + (t + 1) * 16384;
            if (sv0) cp_async4(&sbuf[cur ^ 1][tid],       fr + g0);
            if (sv1) cp_async4(&sbuf[cur ^ 1][tid + 256], fr + g1);
        }
        cp_commit();

        u64_t aA = 0ull, aB = 0ull, aC = 0ull, aD = 0ull;  // (y0x0,y0x1,y1x0,y1x1), ch-pairs
        {
            const float* sp_ = &sbuf[cur][kh * 216 + 2 * xp];
            #pragma unroll
            for (int r = 0; r < 6; ++r) {
                float2 f0 = *(const float2*)(sp_ + r * 36);
                float2 f1 = *(const float2*)(sp_ + r * 36 + 2);
                float2 f2 = *(const float2*)(sp_ + r * 36 + 4);
                u64_t vd[6];
                vd[0] = dup2(f0.x); vd[1] = dup2(f0.y);
                vd[2] = dup2(f1.x); vd[3] = dup2(f1.y);
                vd[4] = dup2(f2.x); vd[5] = dup2(f2.y);
                if (r < 5) {                       // y0: ky = r
                    #pragma unroll
                    for (int kx = 0; kx < 5; ++kx) {
                        aA = fma2(vd[kx],     wp[r * 5 + kx], aA);
                        aB = fma2(vd[kx + 1], wp[r * 5 + kx], aB);
                    }
                }
                if (r >= 1) {                      // y1: ky = r-1
                    #pragma unroll
                    for (int kx = 0; kx < 5; ++kx) {
                        aC = fma2(vd[kx],     wp[(r - 1) * 5 + kx], aC);
                        aD = fma2(vd[kx + 1], wp[(r - 1) * 5 + kx], aD);
                    }
                }
            }
        }
        // combine input-channel halves (commutative add -> lanes identical)
        aA = add2(aA, __shfl_xor_sync(0xffffffffu, aA, 16));
        aB = add2(aB, __shfl_xor_sync(0xffffffffu, aB, 16));
        aC = add2(aC, __shfl_xor_sync(0xffffffffu, aC, 16));
        aD = add2(aD, __shfl_xor_sync(0xffffffffu, aD, 16));

        float sA0, sA1, sB0, sB1, sC0, sC1, sD0, sD1;
        srm2_step(stA, aA, sA0, sA1);
        srm2_step(stB, aB, sB0, sB1);
        srm2_step(stC, aC, sC0, sC1);
        srm2_step(stD, aD, sD0, sD1);
        float u0 = 11.0f * ((sA0 + sB0) + (sC0 + sD0));   // exact small ints
        float u1 = 11.0f * ((sA1 + sB1) + (sC1 + sD1));
        float p0 = srm_step(pl0, u0);
        float p1 = srm_step(pl1, u1);
        if (kh == 0) {
            g_s2[t * 32768 + outIdx]        = p0;
            g_s2[t * 32768 + outIdx + 2048] = p1;
        }

        cp_wait0();
        __syncthreads();
    }
}

// ---------------------------------------------------------------------------
// conv2 (3x3,pad1,16->32) + psp+spike + 2x2 pool + psp+spike, fused.
// grid (hp=8, b=8, xh=2), 256 thr: xp = tid[0:1], kq = tid[2:3], co = tid>>4
// (0..15). Each thread computes channels co and co+16 (f32x2 channel-packed).
// Channel stride padded to 42 floats (kq quarters -> banks {0,8,16,24}).
// kq quarters combined with shfl_xor(4),(8).
// ---------------------------------------------------------------------------
#define C2_CS 42                           // padded channel stride (floats)
__global__ void __launch_bounds__(256) conv2_fused_kernel(const float* __restrict__ W2) {
    __shared__ float sbuf[2][16 * C2_CS];  // [buf][ci*42 + r*10 + c], rows 2hp-1..2hp+2
    const int tid = threadIdx.x;
    const int xp  = tid & 3;
    const int kq  = (tid >> 2) & 3;
    const int co  = tid >> 4;             // 0..15 -> channels co, co+16
    const int hp  = blockIdx.x;           // 0..7
    const int b   = blockIdx.y;
    const int xh  = blockIdx.z;           // 0..1
    u64_t wp[36];
    #pragma unroll
    for (int k = 0; k < 36; ++k)
        wp[k] = pk2(W2[co * 144 + kq * 36 + k], W2[(co + 16) * 144 + kq * 36 + k]);
    for (int i = tid; i < 2 * 16 * C2_CS; i += 256) ((float*)sbuf)[i] = 0.f;

    // staging: slots tid, tid+256, tid+512 (672 total)
    bool sv0 = false, sv1 = false, sv2 = false; int g0 = 0, g1 = 0, g2 = 0;
    #pragma unroll
    for (int e = 0; e < 3; ++e) {
        int i = tid + e * 256;
        if (i >= 16 * C2_CS) break;
        int ci = i / C2_CS, rem = i - ci * C2_CS;
        if (rem < 40) {
            int r = rem / 10, c = rem - r * 10;
            int row = 2 * hp + r - 1, col = xh * 8 + c - 1;
            if (row >= 0 && row < 16 && col >= 0 && col < 16) {
                int g = b * 4096 + ci * 256 + row * 16 + col;
                if (e == 0) { sv0 = true; g0 = g; }
                else if (e == 1) { sv1 = true; g1 = g; }
                else { sv2 = true; g2 = g; }
            }
        }
    }
    __syncthreads();

    if (sv0) cp_async4(&sbuf[0][tid],       g_s2 + g0);
    if (sv1) cp_async4(&sbuf[0][tid + 256], g_s2 + g1);
    if (sv2) cp_async4(&sbuf[0][tid + 512], g_s2 + g2);
    cp_commit(); cp_wait0();
    __syncthreads();

    Srm2 stA = {0,0,0,0}, stB = {0,0,0,0}, stC = {0,0,0,0}, stD = {0,0,0,0};
    Srm  pl0 = {0.f,0.f,0.f,0.f}, pl1 = {0.f,0.f,0.f,0.f};
    const int outIdx = ((b * 32 + co) * 8 + hp) * 8 + xh * 4 + xp;  // ch1 at +1024

    #pragma unroll 1
    for (int t = 0; t < T_STEPS; ++t) {
        const int cur = t & 1;
        if (t + 1 < T_STEPS) {
            const float* fr = g_s2 + (t + 1) * 32768;
            if (sv0) cp_async4(&sbuf[cur ^ 1][tid],       fr + g0);
            if (sv1) cp_async4(&sbuf[cur ^ 1][tid + 256], fr + g1);
            if (sv2) cp_async4(&sbuf[cur ^ 1][tid + 512], fr + g2);
        }
        cp_commit();

        u64_t aA = 0ull, aB = 0ull, aC = 0ull, aD = 0ull;
        #pragma unroll
        for (int lci = 0; lci < 4; ++lci) {
            const float* sp_ = &sbuf[cur][(kq * 4 + lci) * C2_CS + 2 * xp];
            #pragma unroll
            for (int r = 0; r < 4; ++r) {
                float2 f0 = *(const float2*)(sp_ + r * 10);
                float2 f1 = *(const float2*)(sp_ + r * 10 + 2);
                u64_t vd[4];
                vd[0] = dup2(f0.x); vd[1] = dup2(f0.y);
                vd[2] = dup2(f1.x); vd[3] = dup2(f1.y);
                if (r < 3) {                       // y0: ky = r
                    #pragma unroll
                    for (int kx = 0; kx < 3; ++kx) {
                        aA = fma2(vd[kx],     wp[lci * 9 + r * 3 + kx], aA);
                        aB = fma2(vd[kx + 1], wp[lci * 9 + r * 3 + kx], aB);
                    }
                }
                if (r >= 1) {                      // y1: ky = r-1
                    #pragma unroll
                    for (int kx = 0; kx < 3; ++kx) {
                        aC = fma2(vd[kx],     wp[lci * 9 + (r - 1) * 3 + kx], aC);
                        aD = fma2(vd[kx + 1], wp[lci * 9 + (r - 1) * 3 + kx], aD);
                    }
                }
            }
        }
        // combine quarters: ((q0+q1)+(q2+q3)), identical on all 4 lanes
        aA = add2(aA, __shfl_xor_sync(0xffffffffu, aA, 4));
        aB = add2(aB, __shfl_xor_sync(0xffffffffu, aB, 4));
        aC = add2(aC, __shfl_xor_sync(0xffffffffu, aC, 4));
        aD = add2(aD, __shfl_xor_sync(0xffffffffu, aD, 4));
        aA = add2(aA, __shfl_xor_sync(0xffffffffu, aA, 8));
        aB = add2(aB, __shfl_xor_sync(0xffffffffu, aB, 8));
        aC = add2(aC, __shfl_xor_sync(0xffffffffu, aC, 8));
        aD = add2(aD, __shfl_xor_sync(0xffffffffu, aD, 8));

        float sA0, sA1, sB0, sB1, sC0, sC1, sD0, sD1;
        srm2_step(stA, aA, sA0, sA1);
        srm2_step(stB, aB, sB0, sB1);
        srm2_step(stC, aC, sC0, sC1);
        srm2_step(stD, aD, sD0, sD1);
        float u0 = 11.0f * ((sA0 + sB0) + (sC0 + sD0));
        float u1 = 11.0f * ((sA1 + sB1) + (sC1 + sD1));
        float p0 = srm_step(pl0, u0);
        float p1 = srm_step(pl1, u1);
        if (kq == 0) {
            g_s4[t * 16384 + outIdx]        = p0;
            g_s4[t * 16384 + outIdx + 1024] = p1;
        }

        cp_wait0();
        __syncthreads();
    }
}

// ---------------------------------------------------------------------------
// fc1 GEMM: rows=(t,b) 2400, K=2048, N=512. 64x64 tile, 4x4 micro, kc=32,
// register double-buffered global loads, LDS.128 inner loop. 304 blocks.
// ---------------------------------------------------------------------------
__global__ void __launch_bounds__(256) fc1_gemm_kernel(const float* __restrict__ Wf1) {
    __shared__ float As[32 * 68];
    __shared__ float Bs[32 * 68];
    const int tid = threadIdx.x;
    const int txn = tid & 15, tym = tid >> 4;
    const int m0 = blockIdx.x * 64, n0 = blockIdx.y * 64;
    float acc[4][4];
    #pragma unroll
    for (int i = 0; i < 4; ++i)
        #pragma unroll
        for (int j = 0; j < 4; ++j) acc[i][j] = 0.f;

    float4 ra[2], rb[2];
    #pragma unroll
    for (int e = 0; e < 2; ++e) {
        int i = tid + e * 256, m = i >> 3, kq = i & 7, row = m0 + m;
        ra[e] = (row < 2400) ? *(const float4*)(g_s4 + row * 2048 + kq * 4)
                             : make_float4(0.f, 0.f, 0.f, 0.f);
        rb[e] = *(const float4*)(Wf1 + (n0 + m) * 2048 + kq * 4);
    }

    for (int kb = 0; kb < 2048; kb += 32) {
        #pragma unroll
        for (int e = 0; e < 2; ++e) {
            int i = tid + e * 256, m = i >> 3, kq = i & 7;
            As[(kq * 4 + 0) * 68 + m] = ra[e].x;
            As[(kq * 4 + 1) * 68 + m] = ra[e].y;
            As[(kq * 4 + 2) * 68 + m] = ra[e].z;
            As[(kq * 4 + 3) * 68 + m] = ra[e].w;
            Bs[(kq * 4 + 0) * 68 + m] = rb[e].x;
            Bs[(kq * 4 + 1) * 68 + m] = rb[e].y;
            Bs[(kq * 4 + 2) * 68 + m] = rb[e].z;
            Bs[(kq * 4 + 3) * 68 + m] = rb[e].w;
        }
        __syncthreads();
        if (kb + 32 < 2048) {
            #pragma unroll
            for (int e = 0; e < 2; ++e) {
                int i = tid + e * 256, m = i >> 3, kq = i & 7, row = m0 + m;
                ra[e] = (row < 2400) ? *(const float4*)(g_s4 + row * 2048 + kb + 32 + kq * 4)
                                     : make_float4(0.f, 0.f, 0.f, 0.f);
                rb[e] = *(const float4*)(Wf1 + (n0 + m) * 2048 + kb + 32 + kq * 4);
            }
        }
        #pragma unroll
        for (int k = 0; k < 32; ++k) {
            float4 aq = *(const float4*)&As[k * 68 + tym * 4];
            float4 bq = *(const float4*)&Bs[k * 68 + txn * 4];
            float av[4] = {aq.x, aq.y, aq.z, aq.w};
            float bv[4] = {bq.x, bq.y, bq.z, bq.w};
            #pragma unroll
            for (int i = 0; i < 4; ++i)
                #pragma unroll
                for (int j = 0; j < 4; ++j)
                    acc[i][j] = fmaf(av[i], bv[j], acc[i][j]);
        }
        __syncthreads();
    }
    #pragma unroll
    for (int i = 0; i < 4; ++i) {
        int row = m0 + tym * 4 + i;
        if (row < 2400) {
            float4 v = make_float4(acc[i][0], acc[i][1], acc[i][2], acc[i][3]);
            *(float4*)(g_u5 + row * 512 + n0 + txn * 4) = v;
        }
    }
}

// ---------------------------------------------------------------------------
__global__ void fc2_kernel(const float* __restrict__ Wf2) {
    int idx = blockIdx.x * 256 + threadIdx.x;
    if (idx >= 2400 * 11) return;
    int row = idx / 11, o = idx % 11;
    const float* a  = g_u5 + row * 512;
    const float* wv = Wf2 + o * 512;
    float acc = 0.f;
    #pragma unroll 8
    for (int c = 0; c < 512; ++c) acc = fmaf(a[c], wv[c], acc);
    g_u6[idx] = acc;
}

__global__ void final_scan_kernel(float* __restrict__ out) {
    int n = threadIdx.x;
    if (n >= 88) return;
    Srm st = {0.f, 0.f, 0.f, 0.f};
    #pragma unroll 1
    for (int t = 0; t < T_STEPS; ++t) {
        float s = srm_step(st, g_u6[t * 88 + n]);
        out[n * 300 + t] = s;
    }
}

// ---------------------------------------------------------------------------
extern "C" void kernel_launch(void* const* d_in, const int* in_sizes, int n_in,
                              void* d_out, int out_size) {
    (void)in_sizes; (void)n_in; (void)out_size;
    const float* s_in = (const float*)d_in[0];
    const float* W1   = (const float*)d_in[1];
    const float* W2   = (const float*)d_in[2];
    const float* Wf1  = (const float*)d_in[3];
    const float* Wf2  = (const float*)d_in[4];
    float* out = (float*)d_out;

    pool0_transpose_kernel<<<dim3(3, 512), dim3(32, 8)>>>(s_in);
    scan_s0_kernel<<<128, 128>>>();
    conv1_fused_kernel<<<dim3(16, 8), 256>>>(W1);
    conv2_fused_kernel<<<dim3(8, 8, 2), 256>>>(W2);
    fc1_gemm_kernel<<<dim3(38, 8), 256>>>(Wf1);
    scan_u5_kernel<<<32, 128>>>();
    fc2_kernel<<<104, 256>>>(Wf2);
    final_scan_kernel<<<1, 128>>>(out);
}